// round 6
// baseline (speedup 1.0000x reference)
#include <cuda_runtime.h>
#include <math.h>
#include <stdint.h>

#define NN 50000
#define EE 800000
#define FDIM 256   /* HEADS*HID */

// ---------------- scratch (device globals: allowed) ----------------
__device__ float g_ft[(size_t)NN * FDIM];
__device__ float g_x [(size_t)NN * FDIM];
__device__ float g_res[(size_t)NN * FDIM];
__device__ float g_el[NN * 4];
__device__ float g_er[NN * 4];
__device__ float g_hf[NN * 64];
__device__ int   g_deg[NN + 1];
__device__ int   g_off[NN + 1];
__device__ int   g_pos[NN];
__device__ int   g_esrc[EE];
__device__ float g_wt1 [256 * 128];   // W1^T
__device__ float g_wtr [256 * 128];   // Wr1^T
__device__ float g_wt2 [256 * 256];   // W2^T
__device__ float g_wt3 [256 * 256];   // W3^T

__device__ __forceinline__ float lrelu(float x) { return x > 0.f ? x : 0.2f * x; }

// 3xTF32 helpers: split fp32 into tf32 hi/lo (bit patterns in uint32)
__device__ __forceinline__ uint2 tf32_split(float x) {
    uint32_t hi, lo;
    asm("cvt.rna.tf32.f32 %0, %1;" : "=r"(hi) : "f"(x));
    float r = x - __uint_as_float(hi);
    asm("cvt.rna.tf32.f32 %0, %1;" : "=r"(lo) : "f"(r));
    return make_uint2(hi, lo);
}

__device__ __forceinline__ void mma_tf32(float* d,
    uint32_t a0, uint32_t a1, uint32_t a2, uint32_t a3,
    uint32_t b0, uint32_t b1)
{
    asm volatile(
        "mma.sync.aligned.m16n8k8.row.col.f32.tf32.tf32.f32 "
        "{%0,%1,%2,%3}, {%4,%5,%6,%7}, {%8,%9}, {%0,%1,%2,%3};"
        : "+f"(d[0]), "+f"(d[1]), "+f"(d[2]), "+f"(d[3])
        : "r"(a0), "r"(a1), "r"(a2), "r"(a3), "r"(b0), "r"(b1));
}

// ---------------- CSR build ----------------
__global__ void zero_int_kernel(int* __restrict__ p, int n) {
    int i = blockIdx.x * blockDim.x + threadIdx.x;
    if (i < n) p[i] = 0;
}

__global__ void hist_kernel(const int* __restrict__ dst, int* __restrict__ deg, int e) {
    int i = blockIdx.x * blockDim.x + threadIdx.x;
    if (i < e) atomicAdd(&deg[dst[i]], 1);
}

__global__ void scan_kernel(const int* __restrict__ deg, int* __restrict__ off,
                            int* __restrict__ pos, int n) {
    __shared__ int sh[1024];
    int running = 0;
    for (int base = 0; base < n; base += 1024) {
        int i = base + threadIdx.x;
        int v = (i < n) ? deg[i] : 0;
        sh[threadIdx.x] = v;
        __syncthreads();
        for (int o = 1; o < 1024; o <<= 1) {
            int t = (threadIdx.x >= o) ? sh[threadIdx.x - o] : 0;
            __syncthreads();
            sh[threadIdx.x] += t;
            __syncthreads();
        }
        int excl = sh[threadIdx.x] - v;
        if (i < n) { off[i] = running + excl; pos[i] = running + excl; }
        running += sh[1023];
        __syncthreads();
    }
    if (threadIdx.x == 0) off[n] = running;
}

__global__ void scatter_kernel(const int* __restrict__ src, const int* __restrict__ dst,
                               int* __restrict__ pos, int* __restrict__ esrc, int e) {
    int i = blockIdx.x * blockDim.x + threadIdx.x;
    if (i < e) {
        int p = atomicAdd(&pos[dst[i]], 1);
        esrc[p] = src[i];
    }
}

// ---------------- weight transpose: Wt[n][k] = W[k][n] ----------------
__global__ void transpose_kernel(const float* __restrict__ W, float* __restrict__ Wt, int K) {
    __shared__ float tile[32][33];
    int bx = blockIdx.x * 32;   // n base
    int by = blockIdx.y * 32;   // k base
    int x = bx + threadIdx.x;
    #pragma unroll
    for (int j = threadIdx.y; j < 32; j += 8) {
        int y = by + j;
        if (y < K && x < 256) tile[j][threadIdx.x] = W[(size_t)y * 256 + x];
    }
    __syncthreads();
    int xo = by + threadIdx.x;  // k
    #pragma unroll
    for (int j = threadIdx.y; j < 32; j += 8) {
        int yo = bx + j;        // n
        if (yo < 256 && xo < K) Wt[(size_t)yo * K + xo] = tile[threadIdx.x][j];
    }
}

// ---------------- 3xTF32 mma.sync GEMM ----------------
// Y[M,256] = X[M,K] @ Wt[256,K]^T.  CTA tile 128 x 128 (grid.y picks col half),
// BK=32.  smem holds A/B tiles in m16n8k8 fragment order as (hi,lo) uint2.
// Warps: 4(m) x 2(n); warp tile 32x64 = 2 x 8 mma tiles.
// EL: fused attention logits (warp wn owns head blockIdx.y*2 + wn).
template <int K, bool EL>
__global__ void __launch_bounds__(256) gemm_tc(
    const float* __restrict__ X, const float* __restrict__ Wt,
    float* __restrict__ Y,
    const float* __restrict__ al, const float* __restrict__ ar,
    float* __restrict__ el, float* __restrict__ er, int M)
{
    extern __shared__ uint2 sm[];
    uint2* sA = sm;            // [8 mtile][4 kstep][4 reg][32 lane]  = 4096 uint2
    uint2* sB = sm + 4096;     // [16 ntile][4 kstep][2 reg][32 lane] = 4096 uint2
    float* sal = (float*)(sm + 8192);   // 128 floats (2 heads)
    float* sar = sal + 128;

    const int t    = threadIdx.x;
    const int wid  = t >> 5;
    const int lane = t & 31;
    const int wm   = wid & 3;
    const int wn   = wid >> 2;
    const int bm   = blockIdx.x * 128;
    const int bn   = blockIdx.y * 128;

    if (EL && t < 128) {
        sal[t] = al[blockIdx.y * 128 + t];
        sar[t] = ar[blockIdx.y * 128 + t];
    }

    float d[2][8][4];
    #pragma unroll
    for (int mi = 0; mi < 2; mi++)
        #pragma unroll
        for (int j = 0; j < 8; j++)
            #pragma unroll
            for (int q = 0; q < 4; q++) d[mi][j][q] = 0.f;

    const int NCH = K / 32;
    for (int c = 0; c < NCH; c++) {
        // ---- load A tile (128 rows x 32 k) into fragment-order smem ----
        #pragma unroll
        for (int l = 0; l < 4; l++) {
            int idx = t + l * 256;        // 0..1023 float4 slots
            int row = idx >> 3;
            int f4  = idx & 7;
            int gr  = bm + row;
            float4 v = (gr < M) ? *(const float4*)(X + (size_t)gr * K + c * 32 + f4 * 4)
                                : make_float4(0.f, 0.f, 0.f, 0.f);
            int i  = row >> 4, rr = row & 15;
            int s  = f4 >> 1;
            int r  = (rr >> 3) | ((f4 & 1) << 1);
            int base = (((i * 4 + s) * 4 + r) << 5) + (rr & 7) * 4;
            sA[base + 0] = tf32_split(v.x);
            sA[base + 1] = tf32_split(v.y);
            sA[base + 2] = tf32_split(v.z);
            sA[base + 3] = tf32_split(v.w);
        }
        // ---- load B tile (128 n-rows x 32 k) ----
        #pragma unroll
        for (int l = 0; l < 4; l++) {
            int idx = t + l * 256;
            int row = idx >> 3;
            int f4  = idx & 7;
            float4 v = *(const float4*)(Wt + (size_t)(bn + row) * K + c * 32 + f4 * 4);
            int j  = row >> 3, nn = row & 7;
            int s  = f4 >> 1;
            int r  = f4 & 1;
            int base = (((j * 4 + s) * 2 + r) << 5) + nn * 4;
            sB[base + 0] = tf32_split(v.x);
            sB[base + 1] = tf32_split(v.y);
            sB[base + 2] = tf32_split(v.z);
            sB[base + 3] = tf32_split(v.w);
        }
        __syncthreads();

        // ---- consume ----
        #pragma unroll
        for (int s = 0; s < 4; s++) {
            uint2 a[2][4];
            #pragma unroll
            for (int mi = 0; mi < 2; mi++) {
                int i = wm * 2 + mi;
                #pragma unroll
                for (int r = 0; r < 4; r++)
                    a[mi][r] = sA[(((i * 4 + s) * 4 + r) << 5) + lane];
            }
            #pragma unroll
            for (int j = 0; j < 8; j++) {
                int jj = wn * 8 + j;
                uint2 b0 = sB[(((jj * 4 + s) * 2 + 0) << 5) + lane];
                uint2 b1 = sB[(((jj * 4 + s) * 2 + 1) << 5) + lane];
                #pragma unroll
                for (int mi = 0; mi < 2; mi++) {
                    // hi*hi, hi*lo, lo*hi
                    mma_tf32(d[mi][j], a[mi][0].x, a[mi][1].x, a[mi][2].x, a[mi][3].x, b0.x, b1.x);
                    mma_tf32(d[mi][j], a[mi][0].x, a[mi][1].x, a[mi][2].x, a[mi][3].x, b0.y, b1.y);
                    mma_tf32(d[mi][j], a[mi][0].y, a[mi][1].y, a[mi][2].y, a[mi][3].y, b0.x, b1.x);
                }
            }
        }
        __syncthreads();
    }

    // ---- epilogue: write Y (+ fused el/er) ----
    // D frag: {d0,d1} -> row lane/4,   cols (lane%4)*2, +1
    //         {d2,d3} -> row lane/4+8, same cols
    float elA[2][2], erA[2][2];   // [mi][row half]
    #pragma unroll
    for (int mi = 0; mi < 2; mi++) { elA[mi][0] = elA[mi][1] = 0.f; erA[mi][0] = erA[mi][1] = 0.f; }

    #pragma unroll
    for (int mi = 0; mi < 2; mi++) {
        int r0 = bm + wm * 32 + mi * 16 + (lane >> 2);
        #pragma unroll
        for (int j = 0; j < 8; j++) {
            int cb = bn + wn * 64 + j * 8 + (lane & 3) * 2;
            if (r0 < M)
                *(float2*)(Y + (size_t)r0 * 256 + cb) = make_float2(d[mi][j][0], d[mi][j][1]);
            if (r0 + 8 < M)
                *(float2*)(Y + (size_t)(r0 + 8) * 256 + cb) = make_float2(d[mi][j][2], d[mi][j][3]);
            if (EL) {
                int o = wn * 64 + j * 8 + (lane & 3) * 2;
                float a0 = sal[o], a1 = sal[o + 1];
                float r0l = sar[o], r1l = sar[o + 1];
                elA[mi][0] = fmaf(d[mi][j][0], a0, fmaf(d[mi][j][1], a1, elA[mi][0]));
                elA[mi][1] = fmaf(d[mi][j][2], a0, fmaf(d[mi][j][3], a1, elA[mi][1]));
                erA[mi][0] = fmaf(d[mi][j][0], r0l, fmaf(d[mi][j][1], r1l, erA[mi][0]));
                erA[mi][1] = fmaf(d[mi][j][2], r0l, fmaf(d[mi][j][3], r1l, erA[mi][1]));
            }
        }
    }

    if (EL) {
        const int head = blockIdx.y * 2 + wn;
        #pragma unroll
        for (int mi = 0; mi < 2; mi++) {
            #pragma unroll
            for (int hrow = 0; hrow < 2; hrow++) {
                float vl = elA[mi][hrow], vr = erA[mi][hrow];
                vl += __shfl_xor_sync(0xffffffffu, vl, 1);
                vl += __shfl_xor_sync(0xffffffffu, vl, 2);
                vr += __shfl_xor_sync(0xffffffffu, vr, 1);
                vr += __shfl_xor_sync(0xffffffffu, vr, 2);
                if ((lane & 3) == 0) {
                    int rg = bm + wm * 32 + mi * 16 + (lane >> 2) + hrow * 8;
                    if (rg < M) {
                        el[rg * 4 + head] = vl;
                        er[rg * 4 + head] = vr;
                    }
                }
            }
        }
    }
}

// ---------------- per-destination softmax aggregation ----------------
// 2 warps per node; pass 1 max, pass 2 4-deep unrolled accumulate.
template <int MODE>  // 0: relu, write [N,256] ; 1: final, head-mean -> [N,64]
__global__ void __launch_bounds__(256) agg_kernel(
    const int* __restrict__ off, const int* __restrict__ esrc,
    const float* __restrict__ el, const float* __restrict__ er,
    const float* __restrict__ ft, const float* __restrict__ resid,
    float* __restrict__ out, int n)
{
    const int t    = threadIdx.x;
    const int warp = t >> 5;
    const int lane = t & 31;
    const int nl   = warp >> 1;
    const int half = warp & 1;
    const int nid  = blockIdx.x * 4 + nl;
    const bool active = (nid < n);

    __shared__ float4 smA[4][16];
    __shared__ float4 smB[4][16];

    float v0 = 0.f, v1 = 0.f, v2 = 0.f, v3 = 0.f;

    if (active) {
        const int s = off[nid], eEnd = off[nid + 1];
        float2 erp = *(const float2*)(er + nid * 4 + half * 2);

        float mxa = -1e30f, mxb = -1e30f;
        for (int i = s + lane; i < eEnd; i += 32) {
            int sc = esrc[i];
            float2 ep = *(const float2*)(el + sc * 4 + half * 2);
            mxa = fmaxf(mxa, lrelu(ep.x + erp.x));
            mxb = fmaxf(mxb, lrelu(ep.y + erp.y));
        }
        #pragma unroll
        for (int o = 16; o; o >>= 1) {
            mxa = fmaxf(mxa, __shfl_xor_sync(0xffffffffu, mxa, o));
            mxb = fmaxf(mxb, __shfl_xor_sync(0xffffffffu, mxb, o));
        }

        const float m_h  = (lane < 16) ? mxa : mxb;
        const float er_h = (lane < 16) ? erp.x : erp.y;
        const int   hOff = half * 2 + (lane >> 4);
        const int   fidx = half * 32 + lane;

        float den = 0.f;
        float a0 = 0.f, a1 = 0.f, a2 = 0.f, a3 = 0.f;
        const float4* ft4 = (const float4*)ft;

        int i = s;
        for (; i + 3 < eEnd; i += 4) {
            int sc0 = __ldg(esrc + i);
            int sc1 = __ldg(esrc + i + 1);
            int sc2 = __ldg(esrc + i + 2);
            int sc3 = __ldg(esrc + i + 3);
            float e0 = __ldg(el + sc0 * 4 + hOff);
            float e1 = __ldg(el + sc1 * 4 + hOff);
            float e2 = __ldg(el + sc2 * 4 + hOff);
            float e3 = __ldg(el + sc3 * 4 + hOff);
            float4 f0 = ft4[(size_t)sc0 * 64 + fidx];
            float4 f1 = ft4[(size_t)sc1 * 64 + fidx];
            float4 f2 = ft4[(size_t)sc2 * 64 + fidx];
            float4 f3 = ft4[(size_t)sc3 * 64 + fidx];
            float x0 = __expf(lrelu(e0 + er_h) - m_h);
            float x1 = __expf(lrelu(e1 + er_h) - m_h);
            float x2 = __expf(lrelu(e2 + er_h) - m_h);
            float x3 = __expf(lrelu(e3 + er_h) - m_h);
            den += (x0 + x1) + (x2 + x3);
            a0 = fmaf(x0, f0.x, a0); a1 = fmaf(x0, f0.y, a1);
            a2 = fmaf(x0, f0.z, a2); a3 = fmaf(x0, f0.w, a3);
            a0 = fmaf(x1, f1.x, a0); a1 = fmaf(x1, f1.y, a1);
            a2 = fmaf(x1, f1.z, a2); a3 = fmaf(x1, f1.w, a3);
            a0 = fmaf(x2, f2.x, a0); a1 = fmaf(x2, f2.y, a1);
            a2 = fmaf(x2, f2.z, a2); a3 = fmaf(x2, f2.w, a3);
            a0 = fmaf(x3, f3.x, a0); a1 = fmaf(x3, f3.y, a1);
            a2 = fmaf(x3, f3.z, a2); a3 = fmaf(x3, f3.w, a3);
        }
        for (; i < eEnd; i++) {
            int sc = __ldg(esrc + i);
            float ev = lrelu(__ldg(el + sc * 4 + hOff) + er_h);
            float ex = __expf(ev - m_h);
            den += ex;
            float4 f = ft4[(size_t)sc * 64 + fidx];
            a0 = fmaf(ex, f.x, a0); a1 = fmaf(ex, f.y, a1);
            a2 = fmaf(ex, f.z, a2); a3 = fmaf(ex, f.w, a3);
        }

        float inv = (eEnd > s) ? (1.0f / den) : 0.f;
        float4 r = *(const float4*)(resid + (size_t)nid * FDIM + half * 128 + lane * 4);
        v0 = fmaf(a0, inv, r.x);
        v1 = fmaf(a1, inv, r.y);
        v2 = fmaf(a2, inv, r.z);
        v3 = fmaf(a3, inv, r.w);
    }

    if (MODE == 0) {
        if (active) {
            v0 = fmaxf(v0, 0.f); v1 = fmaxf(v1, 0.f);
            v2 = fmaxf(v2, 0.f); v3 = fmaxf(v3, 0.f);
            *(float4*)(out + (size_t)nid * FDIM + half * 128 + lane * 4) =
                make_float4(v0, v1, v2, v3);
        }
    } else {
        v0 += __shfl_xor_sync(0xffffffffu, v0, 16);
        v1 += __shfl_xor_sync(0xffffffffu, v1, 16);
        v2 += __shfl_xor_sync(0xffffffffu, v2, 16);
        v3 += __shfl_xor_sync(0xffffffffu, v3, 16);
        if (lane < 16) {
            if (half) smB[nl][lane] = make_float4(v0, v1, v2, v3);
            else      smA[nl][lane] = make_float4(v0, v1, v2, v3);
        }
        __syncthreads();
        if (half == 0 && lane < 16 && active) {
            float4 a = smA[nl][lane], b = smB[nl][lane];
            *(float4*)(out + (size_t)nid * 64 + lane * 4) =
                make_float4((a.x + b.x) * 0.25f, (a.y + b.y) * 0.25f,
                            (a.z + b.z) * 0.25f, (a.w + b.w) * 0.25f);
        }
    }
}

// ---------------- edge scoring MLP as register-tiled GEMM ----------------
__global__ void __launch_bounds__(256) mlp_kernel(
    const float* __restrict__ hf, const int* __restrict__ src,
    const int* __restrict__ dst, const float* __restrict__ Wm1,
    const float* __restrict__ bm1, const float* __restrict__ Wm2,
    const float* __restrict__ bm2, float* __restrict__ out, int e)
{
    __shared__ float sD[64][68];
    __shared__ float sW[64][64];
    __shared__ float sb[64];
    __shared__ float sW2[64];

    const int t    = threadIdx.x;
    const int warp = t >> 5;
    const int lane = t & 31;
    const int e0   = blockIdx.x * 64;

    for (int i = t; i < 64 * 64; i += 256) sW[i >> 6][i & 63] = Wm1[i];
    if (t < 64) { sb[t] = bm1[t]; sW2[t] = Wm2[t]; }

    #pragma unroll
    for (int j = 0; j < 8; j++) {
        int le  = warp * 8 + j;
        int eid = e0 + le;
        float2 dv;
        if (eid < e) {
            int s = src[eid], d = dst[eid];
            float2 a = *(const float2*)(hf + (size_t)s * 64 + lane * 2);
            float2 b = *(const float2*)(hf + (size_t)d * 64 + lane * 2);
            dv.x = fabsf(a.x - b.x);
            dv.y = fabsf(a.y - b.y);
        } else {
            dv.x = 0.f; dv.y = 0.f;
        }
        *(float2*)&sD[le][lane * 2] = dv;
    }
    __syncthreads();

    const int tx = t & 15;
    const int ty = t >> 4;

    float z[4][4];
    #pragma unroll
    for (int i = 0; i < 4; i++)
        #pragma unroll
        for (int j = 0; j < 4; j++) z[i][j] = sb[tx * 4 + j];

    #pragma unroll 8
    for (int k = 0; k < 64; k++) {
        float4 wv = *(const float4*)&sW[k][tx * 4];
        float d0 = sD[ty * 4 + 0][k];
        float d1 = sD[ty * 4 + 1][k];
        float d2 = sD[ty * 4 + 2][k];
        float d3 = sD[ty * 4 + 3][k];
        z[0][0] = fmaf(d0, wv.x, z[0][0]); z[0][1] = fmaf(d0, wv.y, z[0][1]);
        z[0][2] = fmaf(d0, wv.z, z[0][2]); z[0][3] = fmaf(d0, wv.w, z[0][3]);
        z[1][0] = fmaf(d1, wv.x, z[1][0]); z[1][1] = fmaf(d1, wv.y, z[1][1]);
        z[1][2] = fmaf(d1, wv.z, z[1][2]); z[1][3] = fmaf(d1, wv.w, z[1][3]);
        z[2][0] = fmaf(d2, wv.x, z[2][0]); z[2][1] = fmaf(d2, wv.y, z[2][1]);
        z[2][2] = fmaf(d2, wv.z, z[2][2]); z[2][3] = fmaf(d2, wv.w, z[2][3]);
        z[3][0] = fmaf(d3, wv.x, z[3][0]); z[3][1] = fmaf(d3, wv.y, z[3][1]);
        z[3][2] = fmaf(d3, wv.z, z[3][2]); z[3][3] = fmaf(d3, wv.w, z[3][3]);
    }

    float w2a = sW2[tx * 4 + 0], w2b = sW2[tx * 4 + 1];
    float w2c = sW2[tx * 4 + 2], w2d = sW2[tx * 4 + 3];
    float p[4];
    #pragma unroll
    for (int i = 0; i < 4; i++) {
        p[i] = fmaxf(z[i][0], 0.f) * w2a + fmaxf(z[i][1], 0.f) * w2b
             + fmaxf(z[i][2], 0.f) * w2c + fmaxf(z[i][3], 0.f) * w2d;
        #pragma unroll
        for (int o = 8; o; o >>= 1) p[i] += __shfl_xor_sync(0xffffffffu, p[i], o);
    }
    if (tx == 0) {
        float b2 = bm2[0];
        #pragma unroll
        for (int i = 0; i < 4; i++) {
            int eid = e0 + ty * 4 + i;
            if (eid < e) out[eid] = 1.0f / (1.0f + __expf(-(p[i] + b2)));
        }
    }
}

// ---------------- launch ----------------
extern "C" void kernel_launch(void* const* d_in, const int* in_sizes, int n_in,
                              void* d_out, int out_size)
{
    const float* h   = (const float*)d_in[0];
    const int*   src = (const int*)d_in[1];
    const int*   dst = (const int*)d_in[2];
    const float* W1  = (const float*)d_in[3];
    const float* Wr1 = (const float*)d_in[4];
    const float* al1 = (const float*)d_in[5];
    const float* ar1 = (const float*)d_in[6];
    const float* W2  = (const float*)d_in[7];
    const float* al2 = (const float*)d_in[8];
    const float* ar2 = (const float*)d_in[9];
    const float* W3  = (const float*)d_in[10];
    const float* al3 = (const float*)d_in[11];
    const float* ar3 = (const float*)d_in[12];
    const float* Wm1 = (const float*)d_in[13];
    const float* bm1 = (const float*)d_in[14];
    const float* Wm2 = (const float*)d_in[15];
    const float* bm2 = (const float*)d_in[16];
    float* out = (float*)d_out;

    const int n = in_sizes[0] / 128;   // 50000
    const int e = in_sizes[1];         // 800000

    float *ft, *x, *res, *el, *er, *hfp, *wt1, *wtr, *wt2, *wt3;
    int *deg, *off, *pos, *esrc;
    cudaGetSymbolAddress((void**)&ft,   g_ft);
    cudaGetSymbolAddress((void**)&x,    g_x);
    cudaGetSymbolAddress((void**)&res,  g_res);
    cudaGetSymbolAddress((void**)&el,   g_el);
    cudaGetSymbolAddress((void**)&er,   g_er);
    cudaGetSymbolAddress((void**)&hfp,  g_hf);
    cudaGetSymbolAddress((void**)&deg,  g_deg);
    cudaGetSymbolAddress((void**)&off,  g_off);
    cudaGetSymbolAddress((void**)&pos,  g_pos);
    cudaGetSymbolAddress((void**)&esrc, g_esrc);
    cudaGetSymbolAddress((void**)&wt1,  g_wt1);
    cudaGetSymbolAddress((void**)&wtr,  g_wtr);
    cudaGetSymbolAddress((void**)&wt2,  g_wt2);
    cudaGetSymbolAddress((void**)&wt3,  g_wt3);

    const int GSMEM = 66560;   // 8192 uint2 + 1KB al/ar
    cudaFuncSetAttribute(gemm_tc<128, true >, cudaFuncAttributeMaxDynamicSharedMemorySize, GSMEM);
    cudaFuncSetAttribute(gemm_tc<128, false>, cudaFuncAttributeMaxDynamicSharedMemorySize, GSMEM);
    cudaFuncSetAttribute(gemm_tc<256, true >, cudaFuncAttributeMaxDynamicSharedMemorySize, GSMEM);

    // CSR build (dst-sorted edges)
    zero_int_kernel<<<(n + 1 + 255) / 256, 256>>>(deg, n + 1);
    hist_kernel<<<(e + 255) / 256, 256>>>(dst, deg, e);
    scan_kernel<<<1, 1024>>>(deg, off, pos, n);
    scatter_kernel<<<(e + 255) / 256, 256>>>(src, dst, pos, esrc, e);

    // weight transposes
    {
        dim3 b(32, 8);
        dim3 g128(8, 4), g256(8, 8);
        transpose_kernel<<<g128, b>>>(W1,  wt1, 128);
        transpose_kernel<<<g128, b>>>(Wr1, wtr, 128);
        transpose_kernel<<<g256, b>>>(W2,  wt2, 256);
        transpose_kernel<<<g256, b>>>(W3,  wt3, 256);
    }

    dim3 gg((n + 127) / 128, 2);
    const int ga = (n + 3) / 4;

    // Layer 1
    gemm_tc<128, true ><<<gg, 256, GSMEM>>>(h, wt1, ft,  al1, ar1, el, er, n);
    gemm_tc<128, false><<<gg, 256, GSMEM>>>(h, wtr, res, nullptr, nullptr, nullptr, nullptr, n);
    agg_kernel<0><<<ga, 256>>>(off, esrc, el, er, ft, res, x, n);
    // Layer 2 (identity residual)
    gemm_tc<256, true><<<gg, 256, GSMEM>>>(x, wt2, ft, al2, ar2, el, er, n);
    agg_kernel<0><<<ga, 256>>>(off, esrc, el, er, ft, x, x, n);
    // Layer 3 (identity residual, no activation, head-mean -> hf)
    gemm_tc<256, true><<<gg, 256, GSMEM>>>(x, wt3, ft, al3, ar3, el, er, n);
    agg_kernel<1><<<ga, 256>>>(off, esrc, el, er, ft, x, hfp, n);

    // Edge MLP -> scores
    mlp_kernel<<<(e + 63) / 64, 256>>>(hfp, src, dst, Wm1, bm1, Wm2, bm2, out, e);
}

// round 7
// speedup vs baseline: 1.2519x; 1.2519x over previous
#include <cuda_runtime.h>
#include <math.h>
#include <stdint.h>

#define NN 50000
#define EE 800000
#define FDIM 256   /* HEADS*HID */

typedef unsigned long long u64;

// ---------------- scratch (device globals: allowed) ----------------
__device__ float g_ft[(size_t)NN * FDIM];
__device__ float g_x [(size_t)NN * FDIM];
__device__ float g_res[(size_t)NN * FDIM];
__device__ float g_el[NN * 4];
__device__ float g_er[NN * 4];
__device__ float g_hf[NN * 64];
__device__ int   g_deg[NN + 1];
__device__ int   g_off[NN + 1];
__device__ int   g_pos[NN];
__device__ int   g_esrc[EE];

__device__ __forceinline__ float lrelu(float x) { return x > 0.f ? x : 0.2f * x; }

// ---------------- packed f32x2 helpers (Blackwell FFMA2) ----------------
__device__ __forceinline__ u64 pack2(float lo, float hi) {
    u64 r; asm("mov.b64 %0, {%1, %2};" : "=l"(r) : "f"(lo), "f"(hi)); return r;
}
__device__ __forceinline__ void fma2(u64& d, u64 a, u64 b) {
    asm("fma.rn.f32x2 %0, %1, %2, %0;" : "+l"(d) : "l"(a), "l"(b));
}
__device__ __forceinline__ float2 unpack2(u64 v) {
    float2 f; asm("mov.b64 {%0, %1}, %2;" : "=f"(f.x), "=f"(f.y) : "l"(v)); return f;
}

// ---------------- CSR build ----------------
__global__ void zero_int_kernel(int* __restrict__ p, int n) {
    int i = blockIdx.x * blockDim.x + threadIdx.x;
    if (i < n) p[i] = 0;
}

__global__ void hist_kernel(const int* __restrict__ dst, int* __restrict__ deg, int e) {
    int i = blockIdx.x * blockDim.x + threadIdx.x;
    if (i < e) atomicAdd(&deg[dst[i]], 1);
}

__global__ void scan_kernel(const int* __restrict__ deg, int* __restrict__ off,
                            int* __restrict__ pos, int n) {
    __shared__ int sh[1024];
    int running = 0;
    for (int base = 0; base < n; base += 1024) {
        int i = base + threadIdx.x;
        int v = (i < n) ? deg[i] : 0;
        sh[threadIdx.x] = v;
        __syncthreads();
        for (int o = 1; o < 1024; o <<= 1) {
            int t = (threadIdx.x >= o) ? sh[threadIdx.x - o] : 0;
            __syncthreads();
            sh[threadIdx.x] += t;
            __syncthreads();
        }
        int excl = sh[threadIdx.x] - v;
        if (i < n) { off[i] = running + excl; pos[i] = running + excl; }
        running += sh[1023];
        __syncthreads();
    }
    if (threadIdx.x == 0) off[n] = running;
}

__global__ void scatter_kernel(const int* __restrict__ src, const int* __restrict__ dst,
                               int* __restrict__ pos, int* __restrict__ esrc, int e) {
    int i = blockIdx.x * blockDim.x + threadIdx.x;
    if (i < e) {
        int p = atomicAdd(&pos[dst[i]], 1);
        esrc[p] = src[i];
    }
}

// ---------------- tiled GEMM (f32x2) + fused attention-logit epilogue -------
// Y[M,256] = X[M,K] @ W[K,256]. BM=128, BN=128, BK=32, 8x8 reg tile per thread,
// accumulators packed in pairs along j (4 x u64 per row i).
template <int K, bool EL>
__global__ void __launch_bounds__(256) gemm_tiled(
    const float* __restrict__ X, const float* __restrict__ W,
    float* __restrict__ Y,
    const float* __restrict__ al, const float* __restrict__ ar,
    float* __restrict__ el, float* __restrict__ er, int M)
{
    __shared__ float sX[32][132];
    __shared__ float sW[32][128];

    const int t  = threadIdx.x;
    const int tx = t & 15;
    const int ty = t >> 4;
    const int bm = blockIdx.x * 128;
    const int bn = blockIdx.y * 128;

    int xrow[4], xkk[4], wkk[4], wnn[4];
    #pragma unroll
    for (int l = 0; l < 4; l++) {
        int idx = t + l * 256;
        xrow[l] = idx >> 3;
        xkk[l]  = (idx & 7) * 4;
        wkk[l]  = idx >> 5;
        wnn[l]  = (idx & 31) * 4;
    }

    float4 rx[4], rw[4];
    #pragma unroll
    for (int l = 0; l < 4; l++) {
        int gr = bm + xrow[l];
        rx[l] = (gr < M) ? *(const float4*)(X + (size_t)gr * K + xkk[l])
                         : make_float4(0.f, 0.f, 0.f, 0.f);
        rw[l] = *(const float4*)(W + (size_t)wkk[l] * 256 + bn + wnn[l]);
    }
    #pragma unroll
    for (int l = 0; l < 4; l++) {
        sX[xkk[l] + 0][xrow[l]] = rx[l].x; sX[xkk[l] + 1][xrow[l]] = rx[l].y;
        sX[xkk[l] + 2][xrow[l]] = rx[l].z; sX[xkk[l] + 3][xrow[l]] = rx[l].w;
        *(float4*)&sW[wkk[l]][wnn[l]] = rw[l];
    }
    __syncthreads();

    u64 acc2[8][4];
    #pragma unroll
    for (int i = 0; i < 8; i++)
        #pragma unroll
        for (int jp = 0; jp < 4; jp++) acc2[i][jp] = 0ull;

    for (int k0 = 0; k0 < K; k0 += 32) {
        bool more = (k0 + 32 < K);
        if (more) {
            #pragma unroll
            for (int l = 0; l < 4; l++) {
                int gr = bm + xrow[l];
                rx[l] = (gr < M) ? *(const float4*)(X + (size_t)gr * K + k0 + 32 + xkk[l])
                                 : make_float4(0.f, 0.f, 0.f, 0.f);
                rw[l] = *(const float4*)(W + (size_t)(k0 + 32 + wkk[l]) * 256 + bn + wnn[l]);
            }
        }

        #pragma unroll
        for (int k = 0; k < 32; k++) {
            float4 a0 = *(const float4*)&sX[k][ty * 8];
            float4 a1 = *(const float4*)&sX[k][ty * 8 + 4];
            float4 b0 = *(const float4*)&sW[k][tx * 4];
            float4 b1 = *(const float4*)&sW[k][64 + tx * 4];
            u64 bp[4];
            bp[0] = pack2(b0.x, b0.y); bp[1] = pack2(b0.z, b0.w);
            bp[2] = pack2(b1.x, b1.y); bp[3] = pack2(b1.z, b1.w);
            float a[8] = {a0.x, a0.y, a0.z, a0.w, a1.x, a1.y, a1.z, a1.w};
            #pragma unroll
            for (int i = 0; i < 8; i++) {
                u64 as = pack2(a[i], a[i]);
                fma2(acc2[i][0], as, bp[0]);
                fma2(acc2[i][1], as, bp[1]);
                fma2(acc2[i][2], as, bp[2]);
                fma2(acc2[i][3], as, bp[3]);
            }
        }
        __syncthreads();
        if (more) {
            #pragma unroll
            for (int l = 0; l < 4; l++) {
                sX[xkk[l] + 0][xrow[l]] = rx[l].x; sX[xkk[l] + 1][xrow[l]] = rx[l].y;
                sX[xkk[l] + 2][xrow[l]] = rx[l].z; sX[xkk[l] + 3][xrow[l]] = rx[l].w;
                *(float4*)&sW[wkk[l]][wnn[l]] = rw[l];
            }
            __syncthreads();
        }
    }

    // unpack accumulators
    float acc[8][8];
    #pragma unroll
    for (int i = 0; i < 8; i++)
        #pragma unroll
        for (int jp = 0; jp < 4; jp++) {
            float2 f = unpack2(acc2[i][jp]);
            acc[i][jp * 2]     = f.x;
            acc[i][jp * 2 + 1] = f.y;
        }

    #pragma unroll
    for (int i = 0; i < 8; i++) {
        int gr = bm + ty * 8 + i;
        if (gr < M) {
            float4* yb = (float4*)(Y + (size_t)gr * 256 + bn);
            yb[tx]      = make_float4(acc[i][0], acc[i][1], acc[i][2], acc[i][3]);
            yb[16 + tx] = make_float4(acc[i][4], acc[i][5], acc[i][6], acc[i][7]);
        }
    }

    if (EL) {
        const int h0 = bn >> 6;
        float al0[4], al1[4], ar0[4], ar1[4];
        #pragma unroll
        for (int j = 0; j < 4; j++) {
            al0[j] = al[h0 * 64 + tx * 4 + j];
            al1[j] = al[(h0 + 1) * 64 + tx * 4 + j];
            ar0[j] = ar[h0 * 64 + tx * 4 + j];
            ar1[j] = ar[(h0 + 1) * 64 + tx * 4 + j];
        }
        #pragma unroll
        for (int i = 0; i < 8; i++) {
            float sl0 = 0.f, sl1 = 0.f, sr0 = 0.f, sr1 = 0.f;
            #pragma unroll
            for (int j = 0; j < 4; j++) {
                sl0 = fmaf(acc[i][j],     al0[j], sl0);
                sr0 = fmaf(acc[i][j],     ar0[j], sr0);
                sl1 = fmaf(acc[i][4 + j], al1[j], sl1);
                sr1 = fmaf(acc[i][4 + j], ar1[j], sr1);
            }
            #pragma unroll
            for (int o = 8; o; o >>= 1) {
                sl0 += __shfl_xor_sync(0xffffffffu, sl0, o);
                sl1 += __shfl_xor_sync(0xffffffffu, sl1, o);
                sr0 += __shfl_xor_sync(0xffffffffu, sr0, o);
                sr1 += __shfl_xor_sync(0xffffffffu, sr1, o);
            }
            if (tx == 0) {
                int gr = bm + ty * 8 + i;
                if (gr < M) {
                    el[gr * 4 + h0]     = sl0;
                    el[gr * 4 + h0 + 1] = sl1;
                    er[gr * 4 + h0]     = sr0;
                    er[gr * 4 + h0 + 1] = sr1;
                }
            }
        }
    }
}

// ---------------- per-destination softmax aggregation ----------------
// 2 warps per node; pass 1 max, pass 2 4-deep unrolled accumulate.
template <int MODE>  // 0: relu, write [N,256] ; 1: final, head-mean -> [N,64]
__global__ void __launch_bounds__(256) agg_kernel(
    const int* __restrict__ off, const int* __restrict__ esrc,
    const float* __restrict__ el, const float* __restrict__ er,
    const float* __restrict__ ft, const float* __restrict__ resid,
    float* __restrict__ out, int n)
{
    const int t    = threadIdx.x;
    const int warp = t >> 5;
    const int lane = t & 31;
    const int nl   = warp >> 1;
    const int half = warp & 1;
    const int nid  = blockIdx.x * 4 + nl;
    const bool active = (nid < n);

    __shared__ float4 smA[4][16];
    __shared__ float4 smB[4][16];

    float v0 = 0.f, v1 = 0.f, v2 = 0.f, v3 = 0.f;

    if (active) {
        const int s = off[nid], eEnd = off[nid + 1];
        float2 erp = *(const float2*)(er + nid * 4 + half * 2);

        float mxa = -1e30f, mxb = -1e30f;
        for (int i = s + lane; i < eEnd; i += 32) {
            int sc = esrc[i];
            float2 ep = *(const float2*)(el + sc * 4 + half * 2);
            mxa = fmaxf(mxa, lrelu(ep.x + erp.x));
            mxb = fmaxf(mxb, lrelu(ep.y + erp.y));
        }
        #pragma unroll
        for (int o = 16; o; o >>= 1) {
            mxa = fmaxf(mxa, __shfl_xor_sync(0xffffffffu, mxa, o));
            mxb = fmaxf(mxb, __shfl_xor_sync(0xffffffffu, mxb, o));
        }

        const float m_h  = (lane < 16) ? mxa : mxb;
        const float er_h = (lane < 16) ? erp.x : erp.y;
        const int   hOff = half * 2 + (lane >> 4);
        const int   fidx = half * 32 + lane;

        float den = 0.f;
        float a0 = 0.f, a1 = 0.f, a2 = 0.f, a3 = 0.f;
        const float4* ft4 = (const float4*)ft;

        int i = s;
        for (; i + 3 < eEnd; i += 4) {
            int sc0 = __ldg(esrc + i);
            int sc1 = __ldg(esrc + i + 1);
            int sc2 = __ldg(esrc + i + 2);
            int sc3 = __ldg(esrc + i + 3);
            float e0 = __ldg(el + sc0 * 4 + hOff);
            float e1 = __ldg(el + sc1 * 4 + hOff);
            float e2 = __ldg(el + sc2 * 4 + hOff);
            float e3 = __ldg(el + sc3 * 4 + hOff);
            float4 f0 = ft4[(size_t)sc0 * 64 + fidx];
            float4 f1 = ft4[(size_t)sc1 * 64 + fidx];
            float4 f2 = ft4[(size_t)sc2 * 64 + fidx];
            float4 f3 = ft4[(size_t)sc3 * 64 + fidx];
            float x0 = __expf(lrelu(e0 + er_h) - m_h);
            float x1 = __expf(lrelu(e1 + er_h) - m_h);
            float x2 = __expf(lrelu(e2 + er_h) - m_h);
            float x3 = __expf(lrelu(e3 + er_h) - m_h);
            den += (x0 + x1) + (x2 + x3);
            a0 = fmaf(x0, f0.x, a0); a1 = fmaf(x0, f0.y, a1);
            a2 = fmaf(x0, f0.z, a2); a3 = fmaf(x0, f0.w, a3);
            a0 = fmaf(x1, f1.x, a0); a1 = fmaf(x1, f1.y, a1);
            a2 = fmaf(x1, f1.z, a2); a3 = fmaf(x1, f1.w, a3);
            a0 = fmaf(x2, f2.x, a0); a1 = fmaf(x2, f2.y, a1);
            a2 = fmaf(x2, f2.z, a2); a3 = fmaf(x2, f2.w, a3);
            a0 = fmaf(x3, f3.x, a0); a1 = fmaf(x3, f3.y, a1);
            a2 = fmaf(x3, f3.z, a2); a3 = fmaf(x3, f3.w, a3);
        }
        for (; i < eEnd; i++) {
            int sc = __ldg(esrc + i);
            float ev = lrelu(__ldg(el + sc * 4 + hOff) + er_h);
            float ex = __expf(ev - m_h);
            den += ex;
            float4 f = ft4[(size_t)sc * 64 + fidx];
            a0 = fmaf(ex, f.x, a0); a1 = fmaf(ex, f.y, a1);
            a2 = fmaf(ex, f.z, a2); a3 = fmaf(ex, f.w, a3);
        }

        float inv = (eEnd > s) ? (1.0f / den) : 0.f;
        float4 r = *(const float4*)(resid + (size_t)nid * FDIM + half * 128 + lane * 4);
        v0 = fmaf(a0, inv, r.x);
        v1 = fmaf(a1, inv, r.y);
        v2 = fmaf(a2, inv, r.z);
        v3 = fmaf(a3, inv, r.w);
    }

    if (MODE == 0) {
        if (active) {
            v0 = fmaxf(v0, 0.f); v1 = fmaxf(v1, 0.f);
            v2 = fmaxf(v2, 0.f); v3 = fmaxf(v3, 0.f);
            *(float4*)(out + (size_t)nid * FDIM + half * 128 + lane * 4) =
                make_float4(v0, v1, v2, v3);
        }
    } else {
        v0 += __shfl_xor_sync(0xffffffffu, v0, 16);
        v1 += __shfl_xor_sync(0xffffffffu, v1, 16);
        v2 += __shfl_xor_sync(0xffffffffu, v2, 16);
        v3 += __shfl_xor_sync(0xffffffffu, v3, 16);
        if (lane < 16) {
            if (half) smB[nl][lane] = make_float4(v0, v1, v2, v3);
            else      smA[nl][lane] = make_float4(v0, v1, v2, v3);
        }
        __syncthreads();
        if (half == 0 && lane < 16 && active) {
            float4 a = smA[nl][lane], b = smB[nl][lane];
            *(float4*)(out + (size_t)nid * 64 + lane * 4) =
                make_float4((a.x + b.x) * 0.25f, (a.y + b.y) * 0.25f,
                            (a.z + b.z) * 0.25f, (a.w + b.w) * 0.25f);
        }
    }
}

// ---------------- edge scoring MLP (f32x2 register-tiled GEMM) --------------
__global__ void __launch_bounds__(256) mlp_kernel(
    const float* __restrict__ hf, const int* __restrict__ src,
    const int* __restrict__ dst, const float* __restrict__ Wm1,
    const float* __restrict__ bm1, const float* __restrict__ Wm2,
    const float* __restrict__ bm2, float* __restrict__ out, int e)
{
    __shared__ float sD[64][68];
    __shared__ float sW[64][64];
    __shared__ float sb[64];
    __shared__ float sW2[64];

    const int t    = threadIdx.x;
    const int warp = t >> 5;
    const int lane = t & 31;
    const int e0   = blockIdx.x * 64;

    for (int i = t; i < 64 * 64; i += 256) sW[i >> 6][i & 63] = Wm1[i];
    if (t < 64) { sb[t] = bm1[t]; sW2[t] = Wm2[t]; }

    #pragma unroll
    for (int j = 0; j < 8; j++) {
        int le  = warp * 8 + j;
        int eid = e0 + le;
        float2 dv;
        if (eid < e) {
            int s = src[eid], d = dst[eid];
            float2 a = *(const float2*)(hf + (size_t)s * 64 + lane * 2);
            float2 b = *(const float2*)(hf + (size_t)d * 64 + lane * 2);
            dv.x = fabsf(a.x - b.x);
            dv.y = fabsf(a.y - b.y);
        } else {
            dv.x = 0.f; dv.y = 0.f;
        }
        *(float2*)&sD[le][lane * 2] = dv;
    }
    __syncthreads();

    const int tx = t & 15;
    const int ty = t >> 4;

    u64 zp[4][2];
    {
        u64 b01 = pack2(sb[tx * 4],     sb[tx * 4 + 1]);
        u64 b23 = pack2(sb[tx * 4 + 2], sb[tx * 4 + 3]);
        #pragma unroll
        for (int i = 0; i < 4; i++) { zp[i][0] = b01; zp[i][1] = b23; }
    }

    #pragma unroll 8
    for (int k = 0; k < 64; k++) {
        float4 wv = *(const float4*)&sW[k][tx * 4];
        u64 wp0 = pack2(wv.x, wv.y);
        u64 wp1 = pack2(wv.z, wv.w);
        #pragma unroll
        for (int i = 0; i < 4; i++) {
            float dv = sD[ty * 4 + i][k];
            u64 ds = pack2(dv, dv);
            fma2(zp[i][0], ds, wp0);
            fma2(zp[i][1], ds, wp1);
        }
    }

    float w2a = sW2[tx * 4 + 0], w2b = sW2[tx * 4 + 1];
    float w2c = sW2[tx * 4 + 2], w2d = sW2[tx * 4 + 3];
    float p[4];
    #pragma unroll
    for (int i = 0; i < 4; i++) {
        float2 z01 = unpack2(zp[i][0]);
        float2 z23 = unpack2(zp[i][1]);
        p[i] = fmaxf(z01.x, 0.f) * w2a + fmaxf(z01.y, 0.f) * w2b
             + fmaxf(z23.x, 0.f) * w2c + fmaxf(z23.y, 0.f) * w2d;
        #pragma unroll
        for (int o = 8; o; o >>= 1) p[i] += __shfl_xor_sync(0xffffffffu, p[i], o);
    }
    if (tx == 0) {
        float b2 = bm2[0];
        #pragma unroll
        for (int i = 0; i < 4; i++) {
            int eid = e0 + ty * 4 + i;
            if (eid < e) out[eid] = 1.0f / (1.0f + __expf(-(p[i] + b2)));
        }
    }
}

// ---------------- launch ----------------
extern "C" void kernel_launch(void* const* d_in, const int* in_sizes, int n_in,
                              void* d_out, int out_size)
{
    const float* h   = (const float*)d_in[0];
    const int*   src = (const int*)d_in[1];
    const int*   dst = (const int*)d_in[2];
    const float* W1  = (const float*)d_in[3];
    const float* Wr1 = (const float*)d_in[4];
    const float* al1 = (const float*)d_in[5];
    const float* ar1 = (const float*)d_in[6];
    const float* W2  = (const float*)d_in[7];
    const float* al2 = (const float*)d_in[8];
    const float* ar2 = (const float*)d_in[9];
    const float* W3  = (const float*)d_in[10];
    const float* al3 = (const float*)d_in[11];
    const float* ar3 = (const float*)d_in[12];
    const float* Wm1 = (const float*)d_in[13];
    const float* bm1 = (const float*)d_in[14];
    const float* Wm2 = (const float*)d_in[15];
    const float* bm2 = (const float*)d_in[16];
    float* out = (float*)d_out;

    const int n = in_sizes[0] / 128;   // 50000
    const int e = in_sizes[1];         // 800000

    float *ft, *x, *res, *el, *er, *hfp;
    int *deg, *off, *pos, *esrc;
    cudaGetSymbolAddress((void**)&ft,   g_ft);
    cudaGetSymbolAddress((void**)&x,    g_x);
    cudaGetSymbolAddress((void**)&res,  g_res);
    cudaGetSymbolAddress((void**)&el,   g_el);
    cudaGetSymbolAddress((void**)&er,   g_er);
    cudaGetSymbolAddress((void**)&hfp,  g_hf);
    cudaGetSymbolAddress((void**)&deg,  g_deg);
    cudaGetSymbolAddress((void**)&off,  g_off);
    cudaGetSymbolAddress((void**)&pos,  g_pos);
    cudaGetSymbolAddress((void**)&esrc, g_esrc);

    // CSR build (dst-sorted edges)
    zero_int_kernel<<<(n + 1 + 255) / 256, 256>>>(deg, n + 1);
    hist_kernel<<<(e + 255) / 256, 256>>>(dst, deg, e);
    scan_kernel<<<1, 1024>>>(deg, off, pos, n);
    scatter_kernel<<<(e + 255) / 256, 256>>>(src, dst, pos, esrc, e);

    dim3 gg((n + 127) / 128, 2);
    const int ga = (n + 3) / 4;

    // Layer 1
    gemm_tiled<128, true ><<<gg, 256>>>(h, W1,  ft,  al1, ar1, el, er, n);
    gemm_tiled<128, false><<<gg, 256>>>(h, Wr1, res, nullptr, nullptr, nullptr, nullptr, n);
    agg_kernel<0><<<ga, 256>>>(off, esrc, el, er, ft, res, x, n);
    // Layer 2 (identity residual)
    gemm_tiled<256, true><<<gg, 256>>>(x, W2, ft, al2, ar2, el, er, n);
    agg_kernel<0><<<ga, 256>>>(off, esrc, el, er, ft, x, x, n);
    // Layer 3 (identity residual, no activation, head-mean -> hf)
    gemm_tiled<256, true><<<gg, 256>>>(x, W3, ft, al3, ar3, el, er, n);
    agg_kernel<1><<<ga, 256>>>(off, esrc, el, er, ft, x, hfp, n);

    // Edge MLP -> scores
    mlp_kernel<<<(e + 63) / 64, 256>>>(hfp, src, dst, Wm1, bm1, Wm2, bm2, out, e);
}

// round 8
// speedup vs baseline: 1.2894x; 1.0299x over previous
#include <cuda_runtime.h>
#include <math.h>
#include <stdint.h>

#define NN 50000
#define EE 800000
#define FDIM 256   /* HEADS*HID */

// ---------------- scratch (device globals: allowed) ----------------
__device__ float g_ft[(size_t)NN * FDIM];
__device__ float g_x [(size_t)NN * FDIM];
__device__ float g_res[(size_t)NN * FDIM];
__device__ float g_el[NN * 4];
__device__ float g_er[NN * 4];
__device__ float g_hf[NN * 64];
__device__ int   g_deg[NN + 1];
__device__ int   g_off[NN + 1];
__device__ int   g_pos[NN];
__device__ int   g_esrc[EE];

__device__ __forceinline__ float lrelu(float x) { return x > 0.f ? x : 0.2f * x; }

__device__ __forceinline__ uint32_t f2tf32(float x) {
    uint32_t r; asm("cvt.rna.tf32.f32 %0, %1;" : "=r"(r) : "f"(x)); return r;
}

__device__ __forceinline__ void mma_tf32(float* d, const uint32_t* a, uint32_t b0, uint32_t b1) {
    asm volatile(
        "mma.sync.aligned.m16n8k8.row.col.f32.tf32.tf32.f32 "
        "{%0,%1,%2,%3}, {%4,%5,%6,%7}, {%8,%9}, {%0,%1,%2,%3};"
        : "+f"(d[0]), "+f"(d[1]), "+f"(d[2]), "+f"(d[3])
        : "r"(a[0]), "r"(a[1]), "r"(a[2]), "r"(a[3]), "r"(b0), "r"(b1));
}

// ---------------- CSR build ----------------
__global__ void zero_int_kernel(int* __restrict__ p, int n) {
    int i = blockIdx.x * blockDim.x + threadIdx.x;
    if (i < n) p[i] = 0;
}

__global__ void hist_kernel(const int* __restrict__ dst, int* __restrict__ deg, int e) {
    int i = blockIdx.x * blockDim.x + threadIdx.x;
    if (i < e) atomicAdd(&deg[dst[i]], 1);
}

__global__ void scan_kernel(const int* __restrict__ deg, int* __restrict__ off,
                            int* __restrict__ pos, int n) {
    __shared__ int sh[1024];
    int running = 0;
    for (int base = 0; base < n; base += 1024) {
        int i = base + threadIdx.x;
        int v = (i < n) ? deg[i] : 0;
        sh[threadIdx.x] = v;
        __syncthreads();
        for (int o = 1; o < 1024; o <<= 1) {
            int t = (threadIdx.x >= o) ? sh[threadIdx.x - o] : 0;
            __syncthreads();
            sh[threadIdx.x] += t;
            __syncthreads();
        }
        int excl = sh[threadIdx.x] - v;
        if (i < n) { off[i] = running + excl; pos[i] = running + excl; }
        running += sh[1023];
        __syncthreads();
    }
    if (threadIdx.x == 0) off[n] = running;
}

__global__ void scatter_kernel(const int* __restrict__ src, const int* __restrict__ dst,
                               int* __restrict__ pos, int* __restrict__ esrc, int e) {
    int i = blockIdx.x * blockDim.x + threadIdx.x;
    if (i < e) {
        int p = atomicAdd(&pos[dst[i]], 1);
        esrc[p] = src[i];
    }
}

// ---------------- single-pass TF32 mma GEMM ----------------
// Y[M,256] = X[M,K] @ W[K,256].  CTA tile 128m x 128n (grid.y = col half), BK=32.
// smem fragment order: A [8 mtile][4 kstep][32 lane][4 reg]  (16KB)
//                      B [16 ntile][4 kstep][32 lane][2 reg] (16KB)
// Warps 4(m) x 2(n); warp tile 32x64 = 2 x 8 m16n8k8 tiles; 1 MMA per tile per kstep.
// EL: fused attention logits (warp wn owns head blockIdx.y*2 + wn).
template <int K, bool EL>
__global__ void __launch_bounds__(256) gemm_tc(
    const float* __restrict__ X, const float* __restrict__ W,
    float* __restrict__ Y,
    const float* __restrict__ al, const float* __restrict__ ar,
    float* __restrict__ el, float* __restrict__ er, int M)
{
    __shared__ uint32_t sA[4096];
    __shared__ uint32_t sB[4096];
    __shared__ float sal[128], sar[128];

    const int t    = threadIdx.x;
    const int wid  = t >> 5;
    const int lane = t & 31;
    const int wm   = wid & 3;
    const int wn   = wid >> 2;
    const int bm   = blockIdx.x * 128;
    const int bn   = blockIdx.y * 128;

    if (EL && t < 128) {
        sal[t] = al[blockIdx.y * 128 + t];
        sar[t] = ar[blockIdx.y * 128 + t];
    }

    // per-thread tile-load coordinates
    const int arow = t >> 1;                 // A: idx = t + l*256 -> row = idx>>3
    // (recomputed in loop; kept simple)

    float d[2][8][4];
    #pragma unroll
    for (int mi = 0; mi < 2; mi++)
        #pragma unroll
        for (int j = 0; j < 8; j++)
            #pragma unroll
            for (int q = 0; q < 4; q++) d[mi][j][q] = 0.f;
    (void)arow;

    float4 rxA[4], rxB[4];
    // preload chunk 0
    #pragma unroll
    for (int l = 0; l < 4; l++) {
        int idx = t + l * 256;
        int row = idx >> 3, f4 = idx & 7;
        int gr  = bm + row;
        rxA[l] = (gr < M) ? *(const float4*)(X + (size_t)gr * K + f4 * 4)
                          : make_float4(0.f, 0.f, 0.f, 0.f);
        int kk = idx >> 5, nn4 = idx & 31;
        rxB[l] = *(const float4*)(W + (size_t)kk * 256 + bn + nn4 * 4);
    }

    const int NCH = K / 32;
    for (int c = 0; c < NCH; c++) {
        // ---- store current chunk's fragments to smem ----
        #pragma unroll
        for (int l = 0; l < 4; l++) {
            int idx = t + l * 256;
            int row = idx >> 3, f4 = idx & 7;
            int i   = row >> 4;
            int rr8 = (row >> 3) & 1;
            int rq  = row & 7;
            int s   = f4 >> 1;
            int rb  = rr8 | ((f4 & 1) << 1);
            int base = (i * 4 + s) * 128 + rq * 16 + rb;
            float4 v = rxA[l];
            sA[base +  0] = f2tf32(v.x);
            sA[base +  4] = f2tf32(v.y);
            sA[base +  8] = f2tf32(v.z);
            sA[base + 12] = f2tf32(v.w);
        }
        #pragma unroll
        for (int l = 0; l < 4; l++) {
            int idx = t + l * 256;
            int kk = idx >> 5, nn4 = idx & 31;
            int s  = kk >> 3, cc = kk & 7;
            int r  = (cc >> 2) & 1, c3 = cc & 3;
            int j  = (nn4 * 4) >> 3;
            int base = (j * 4 + s) * 64 + ((nn4 & 1) * 4) * 8 + c3 * 2 + r;
            float4 v = rxB[l];
            sB[base +  0] = f2tf32(v.x);
            sB[base +  8] = f2tf32(v.y);
            sB[base + 16] = f2tf32(v.z);
            sB[base + 24] = f2tf32(v.w);
        }
        __syncthreads();

        // ---- prefetch next chunk ----
        bool more = (c + 1 < NCH);
        if (more) {
            #pragma unroll
            for (int l = 0; l < 4; l++) {
                int idx = t + l * 256;
                int row = idx >> 3, f4 = idx & 7;
                int gr  = bm + row;
                rxA[l] = (gr < M) ? *(const float4*)(X + (size_t)gr * K + (c + 1) * 32 + f4 * 4)
                                  : make_float4(0.f, 0.f, 0.f, 0.f);
                int kk = idx >> 5, nn4 = idx & 31;
                rxB[l] = *(const float4*)(W + (size_t)((c + 1) * 32 + kk) * 256 + bn + nn4 * 4);
            }
        }

        // ---- consume ----
        #pragma unroll
        for (int s = 0; s < 4; s++) {
            uint4 af[2];
            #pragma unroll
            for (int mi = 0; mi < 2; mi++) {
                int i = wm * 2 + mi;
                af[mi] = *(const uint4*)&sA[(i * 4 + s) * 128 + lane * 4];
            }
            #pragma unroll
            for (int j = 0; j < 8; j++) {
                int jj = wn * 8 + j;
                uint2 bf = *(const uint2*)&sB[(jj * 4 + s) * 64 + lane * 2];
                mma_tf32(d[0][j], (const uint32_t*)&af[0], bf.x, bf.y);
                mma_tf32(d[1][j], (const uint32_t*)&af[1], bf.x, bf.y);
            }
        }
        __syncthreads();
    }

    // ---- epilogue: write Y (+ fused el/er) ----
    float elA[2][2], erA[2][2];
    #pragma unroll
    for (int mi = 0; mi < 2; mi++) { elA[mi][0] = elA[mi][1] = 0.f; erA[mi][0] = erA[mi][1] = 0.f; }

    #pragma unroll
    for (int mi = 0; mi < 2; mi++) {
        int r0 = bm + wm * 32 + mi * 16 + (lane >> 2);
        #pragma unroll
        for (int j = 0; j < 8; j++) {
            int cb = bn + wn * 64 + j * 8 + (lane & 3) * 2;
            if (r0 < M)
                *(float2*)(Y + (size_t)r0 * 256 + cb) = make_float2(d[mi][j][0], d[mi][j][1]);
            if (r0 + 8 < M)
                *(float2*)(Y + (size_t)(r0 + 8) * 256 + cb) = make_float2(d[mi][j][2], d[mi][j][3]);
            if (EL) {
                int o = wn * 64 + j * 8 + (lane & 3) * 2;
                float a0 = sal[o], a1 = sal[o + 1];
                float r0l = sar[o], r1l = sar[o + 1];
                elA[mi][0] = fmaf(d[mi][j][0], a0, fmaf(d[mi][j][1], a1, elA[mi][0]));
                elA[mi][1] = fmaf(d[mi][j][2], a0, fmaf(d[mi][j][3], a1, elA[mi][1]));
                erA[mi][0] = fmaf(d[mi][j][0], r0l, fmaf(d[mi][j][1], r1l, erA[mi][0]));
                erA[mi][1] = fmaf(d[mi][j][2], r0l, fmaf(d[mi][j][3], r1l, erA[mi][1]));
            }
        }
    }

    if (EL) {
        const int head = blockIdx.y * 2 + wn;
        #pragma unroll
        for (int mi = 0; mi < 2; mi++) {
            #pragma unroll
            for (int hrow = 0; hrow < 2; hrow++) {
                float vl = elA[mi][hrow], vr = erA[mi][hrow];
                vl += __shfl_xor_sync(0xffffffffu, vl, 1);
                vl += __shfl_xor_sync(0xffffffffu, vl, 2);
                vr += __shfl_xor_sync(0xffffffffu, vr, 1);
                vr += __shfl_xor_sync(0xffffffffu, vr, 2);
                if ((lane & 3) == 0) {
                    int rg = bm + wm * 32 + mi * 16 + (lane >> 2) + hrow * 8;
                    if (rg < M) {
                        el[rg * 4 + head] = vl;
                        er[rg * 4 + head] = vr;
                    }
                }
            }
        }
    }
}

// ---------------- per-destination softmax aggregation ----------------
template <int MODE>  // 0: relu, write [N,256] ; 1: final, head-mean -> [N,64]
__global__ void __launch_bounds__(256) agg_kernel(
    const int* __restrict__ off, const int* __restrict__ esrc,
    const float* __restrict__ el, const float* __restrict__ er,
    const float* __restrict__ ft, const float* __restrict__ resid,
    float* __restrict__ out, int n)
{
    const int t    = threadIdx.x;
    const int warp = t >> 5;
    const int lane = t & 31;
    const int nl   = warp >> 1;
    const int half = warp & 1;
    const int nid  = blockIdx.x * 4 + nl;
    const bool active = (nid < n);

    __shared__ float4 smA[4][16];
    __shared__ float4 smB[4][16];

    float v0 = 0.f, v1 = 0.f, v2 = 0.f, v3 = 0.f;

    if (active) {
        const int s = off[nid], eEnd = off[nid + 1];
        float2 erp = *(const float2*)(er + nid * 4 + half * 2);

        float mxa = -1e30f, mxb = -1e30f;
        for (int i = s + lane; i < eEnd; i += 32) {
            int sc = esrc[i];
            float2 ep = *(const float2*)(el + sc * 4 + half * 2);
            mxa = fmaxf(mxa, lrelu(ep.x + erp.x));
            mxb = fmaxf(mxb, lrelu(ep.y + erp.y));
        }
        #pragma unroll
        for (int o = 16; o; o >>= 1) {
            mxa = fmaxf(mxa, __shfl_xor_sync(0xffffffffu, mxa, o));
            mxb = fmaxf(mxb, __shfl_xor_sync(0xffffffffu, mxb, o));
        }

        const float m_h  = (lane < 16) ? mxa : mxb;
        const float er_h = (lane < 16) ? erp.x : erp.y;
        const int   hOff = half * 2 + (lane >> 4);
        const int   fidx = half * 32 + lane;

        float den = 0.f;
        float a0 = 0.f, a1 = 0.f, a2 = 0.f, a3 = 0.f;
        const float4* ft4 = (const float4*)ft;

        int i = s;
        for (; i + 3 < eEnd; i += 4) {
            int sc0 = __ldg(esrc + i);
            int sc1 = __ldg(esrc + i + 1);
            int sc2 = __ldg(esrc + i + 2);
            int sc3 = __ldg(esrc + i + 3);
            float e0 = __ldg(el + sc0 * 4 + hOff);
            float e1 = __ldg(el + sc1 * 4 + hOff);
            float e2 = __ldg(el + sc2 * 4 + hOff);
            float e3 = __ldg(el + sc3 * 4 + hOff);
            float4 f0 = ft4[(size_t)sc0 * 64 + fidx];
            float4 f1 = ft4[(size_t)sc1 * 64 + fidx];
            float4 f2 = ft4[(size_t)sc2 * 64 + fidx];
            float4 f3 = ft4[(size_t)sc3 * 64 + fidx];
            float x0 = __expf(lrelu(e0 + er_h) - m_h);
            float x1 = __expf(lrelu(e1 + er_h) - m_h);
            float x2 = __expf(lrelu(e2 + er_h) - m_h);
            float x3 = __expf(lrelu(e3 + er_h) - m_h);
            den += (x0 + x1) + (x2 + x3);
            a0 = fmaf(x0, f0.x, a0); a1 = fmaf(x0, f0.y, a1);
            a2 = fmaf(x0, f0.z, a2); a3 = fmaf(x0, f0.w, a3);
            a0 = fmaf(x1, f1.x, a0); a1 = fmaf(x1, f1.y, a1);
            a2 = fmaf(x1, f1.z, a2); a3 = fmaf(x1, f1.w, a3);
            a0 = fmaf(x2, f2.x, a0); a1 = fmaf(x2, f2.y, a1);
            a2 = fmaf(x2, f2.z, a2); a3 = fmaf(x2, f2.w, a3);
            a0 = fmaf(x3, f3.x, a0); a1 = fmaf(x3, f3.y, a1);
            a2 = fmaf(x3, f3.z, a2); a3 = fmaf(x3, f3.w, a3);
        }
        for (; i < eEnd; i++) {
            int sc = __ldg(esrc + i);
            float ev = lrelu(__ldg(el + sc * 4 + hOff) + er_h);
            float ex = __expf(ev - m_h);
            den += ex;
            float4 f = ft4[(size_t)sc * 64 + fidx];
            a0 = fmaf(ex, f.x, a0); a1 = fmaf(ex, f.y, a1);
            a2 = fmaf(ex, f.z, a2); a3 = fmaf(ex, f.w, a3);
        }

        float inv = (eEnd > s) ? (1.0f / den) : 0.f;
        float4 r = *(const float4*)(resid + (size_t)nid * FDIM + half * 128 + lane * 4);
        v0 = fmaf(a0, inv, r.x);
        v1 = fmaf(a1, inv, r.y);
        v2 = fmaf(a2, inv, r.z);
        v3 = fmaf(a3, inv, r.w);
    }

    if (MODE == 0) {
        if (active) {
            v0 = fmaxf(v0, 0.f); v1 = fmaxf(v1, 0.f);
            v2 = fmaxf(v2, 0.f); v3 = fmaxf(v3, 0.f);
            *(float4*)(out + (size_t)nid * FDIM + half * 128 + lane * 4) =
                make_float4(v0, v1, v2, v3);
        }
    } else {
        v0 += __shfl_xor_sync(0xffffffffu, v0, 16);
        v1 += __shfl_xor_sync(0xffffffffu, v1, 16);
        v2 += __shfl_xor_sync(0xffffffffu, v2, 16);
        v3 += __shfl_xor_sync(0xffffffffu, v3, 16);
        if (lane < 16) {
            if (half) smB[nl][lane] = make_float4(v0, v1, v2, v3);
            else      smA[nl][lane] = make_float4(v0, v1, v2, v3);
        }
        __syncthreads();
        if (half == 0 && lane < 16 && active) {
            float4 a = smA[nl][lane], b = smB[nl][lane];
            *(float4*)(out + (size_t)nid * 64 + lane * 4) =
                make_float4((a.x + b.x) * 0.25f, (a.y + b.y) * 0.25f,
                            (a.z + b.z) * 0.25f, (a.w + b.w) * 0.25f);
        }
    }
}

// ---------------- edge scoring MLP as register-tiled GEMM ----------------
__global__ void __launch_bounds__(256) mlp_kernel(
    const float* __restrict__ hf, const int* __restrict__ src,
    const int* __restrict__ dst, const float* __restrict__ Wm1,
    const float* __restrict__ bm1, const float* __restrict__ Wm2,
    const float* __restrict__ bm2, float* __restrict__ out, int e)
{
    __shared__ float sD[64][68];
    __shared__ float sW[64][64];
    __shared__ float sb[64];
    __shared__ float sW2[64];

    const int t    = threadIdx.x;
    const int warp = t >> 5;
    const int lane = t & 31;
    const int e0   = blockIdx.x * 64;

    for (int i = t; i < 64 * 64; i += 256) sW[i >> 6][i & 63] = Wm1[i];
    if (t < 64) { sb[t] = bm1[t]; sW2[t] = Wm2[t]; }

    #pragma unroll
    for (int j = 0; j < 8; j++) {
        int le  = warp * 8 + j;
        int eid = e0 + le;
        float2 dv;
        if (eid < e) {
            int s = src[eid], d = dst[eid];
            float2 a = *(const float2*)(hf + (size_t)s * 64 + lane * 2);
            float2 b = *(const float2*)(hf + (size_t)d * 64 + lane * 2);
            dv.x = fabsf(a.x - b.x);
            dv.y = fabsf(a.y - b.y);
        } else {
            dv.x = 0.f; dv.y = 0.f;
        }
        *(float2*)&sD[le][lane * 2] = dv;
    }
    __syncthreads();

    const int tx = t & 15;
    const int ty = t >> 4;

    float z[4][4];
    #pragma unroll
    for (int i = 0; i < 4; i++)
        #pragma unroll
        for (int j = 0; j < 4; j++) z[i][j] = sb[tx * 4 + j];

    #pragma unroll 8
    for (int k = 0; k < 64; k++) {
        float4 wv = *(const float4*)&sW[k][tx * 4];
        float d0 = sD[ty * 4 + 0][k];
        float d1 = sD[ty * 4 + 1][k];
        float d2 = sD[ty * 4 + 2][k];
        float d3 = sD[ty * 4 + 3][k];
        z[0][0] = fmaf(d0, wv.x, z[0][0]); z[0][1] = fmaf(d0, wv.y, z[0][1]);
        z[0][2] = fmaf(d0, wv.z, z[0][2]); z[0][3] = fmaf(d0, wv.w, z[0][3]);
        z[1][0] = fmaf(d1, wv.x, z[1][0]); z[1][1] = fmaf(d1, wv.y, z[1][1]);
        z[1][2] = fmaf(d1, wv.z, z[1][2]); z[1][3] = fmaf(d1, wv.w, z[1][3]);
        z[2][0] = fmaf(d2, wv.x, z[2][0]); z[2][1] = fmaf(d2, wv.y, z[2][1]);
        z[2][2] = fmaf(d2, wv.z, z[2][2]); z[2][3] = fmaf(d2, wv.w, z[2][3]);
        z[3][0] = fmaf(d3, wv.x, z[3][0]); z[3][1] = fmaf(d3, wv.y, z[3][1]);
        z[3][2] = fmaf(d3, wv.z, z[3][2]); z[3][3] = fmaf(d3, wv.w, z[3][3]);
    }

    float w2a = sW2[tx * 4 + 0], w2b = sW2[tx * 4 + 1];
    float w2c = sW2[tx * 4 + 2], w2d = sW2[tx * 4 + 3];
    float p[4];
    #pragma unroll
    for (int i = 0; i < 4; i++) {
        p[i] = fmaxf(z[i][0], 0.f) * w2a + fmaxf(z[i][1], 0.f) * w2b
             + fmaxf(z[i][2], 0.f) * w2c + fmaxf(z[i][3], 0.f) * w2d;
        #pragma unroll
        for (int o = 8; o; o >>= 1) p[i] += __shfl_xor_sync(0xffffffffu, p[i], o);
    }
    if (tx == 0) {
        float b2 = bm2[0];
        #pragma unroll
        for (int i = 0; i < 4; i++) {
            int eid = e0 + ty * 4 + i;
            if (eid < e) out[eid] = 1.0f / (1.0f + __expf(-(p[i] + b2)));
        }
    }
}

// ---------------- launch ----------------
extern "C" void kernel_launch(void* const* d_in, const int* in_sizes, int n_in,
                              void* d_out, int out_size)
{
    const float* h   = (const float*)d_in[0];
    const int*   src = (const int*)d_in[1];
    const int*   dst = (const int*)d_in[2];
    const float* W1  = (const float*)d_in[3];
    const float* Wr1 = (const float*)d_in[4];
    const float* al1 = (const float*)d_in[5];
    const float* ar1 = (const float*)d_in[6];
    const float* W2  = (const float*)d_in[7];
    const float* al2 = (const float*)d_in[8];
    const float* ar2 = (const float*)d_in[9];
    const float* W3  = (const float*)d_in[10];
    const float* al3 = (const float*)d_in[11];
    const float* ar3 = (const float*)d_in[12];
    const float* Wm1 = (const float*)d_in[13];
    const float* bm1 = (const float*)d_in[14];
    const float* Wm2 = (const float*)d_in[15];
    const float* bm2 = (const float*)d_in[16];
    float* out = (float*)d_out;

    const int n = in_sizes[0] / 128;   // 50000
    const int e = in_sizes[1];         // 800000

    float *ft, *x, *res, *el, *er, *hfp;
    int *deg, *off, *pos, *esrc;
    cudaGetSymbolAddress((void**)&ft,   g_ft);
    cudaGetSymbolAddress((void**)&x,    g_x);
    cudaGetSymbolAddress((void**)&res,  g_res);
    cudaGetSymbolAddress((void**)&el,   g_el);
    cudaGetSymbolAddress((void**)&er,   g_er);
    cudaGetSymbolAddress((void**)&hfp,  g_hf);
    cudaGetSymbolAddress((void**)&deg,  g_deg);
    cudaGetSymbolAddress((void**)&off,  g_off);
    cudaGetSymbolAddress((void**)&pos,  g_pos);
    cudaGetSymbolAddress((void**)&esrc, g_esrc);

    dim3 gg((n + 127) / 128, 2);
    const int ga = (n + 3) / 4;

    // CSR prefix (scan) first, then layer-1 GEMMs in the ncu-profiled slot,
    // then scatter (must precede agg; stream order guarantees it).
    zero_int_kernel<<<(n + 1 + 255) / 256, 256>>>(deg, n + 1);
    hist_kernel<<<(e + 255) / 256, 256>>>(dst, deg, e);
    scan_kernel<<<1, 1024>>>(deg, off, pos, n);

    gemm_tc<128, true ><<<gg, 256>>>(h, W1,  ft,  al1, ar1, el, er, n);   // profiled slot
    gemm_tc<128, false><<<gg, 256>>>(h, Wr1, res, nullptr, nullptr, nullptr, nullptr, n);

    scatter_kernel<<<(e + 255) / 256, 256>>>(src, dst, pos, esrc, e);

    agg_kernel<0><<<ga, 256>>>(off, esrc, el, er, ft, res, x, n);
    // Layer 2 (identity residual)
    gemm_tc<256, true><<<gg, 256>>>(x, W2, ft, al2, ar2, el, er, n);
    agg_kernel<0><<<ga, 256>>>(off, esrc, el, er, ft, x, x, n);
    // Layer 3 (identity residual, no activation, head-mean -> hf)
    gemm_tc<256, true><<<gg, 256>>>(x, W3, ft, al3, ar3, el, er, n);
    agg_kernel<1><<<ga, 256>>>(off, esrc, el, er, ft, x, hfp, n);

    // Edge MLP -> scores
    mlp_kernel<<<(e + 63) / 64, 256>>>(hfp, src, dst, Wm1, bm1, Wm2, bm2, out, e);
}

// round 9
// speedup vs baseline: 1.8509x; 1.4355x over previous
#include <cuda_runtime.h>
#include <math.h>
#include <stdint.h>

#define NN 50000
#define EE 800000
#define FDIM 256   /* HEADS*HID */

// ---------------- scratch (device globals: allowed) ----------------
__device__ float g_ft[(size_t)NN * FDIM];
__device__ float g_x [(size_t)NN * FDIM];
__device__ float g_res[(size_t)NN * FDIM];
__device__ float g_el[NN * 4];
__device__ float g_er[NN * 4];
__device__ float g_hf[NN * 64];
__device__ int   g_deg[NN + 1];
__device__ int   g_off[NN + 1];
__device__ int   g_pos[NN];
__device__ int   g_esrc[EE];

__device__ __forceinline__ float lrelu(float x) { return x > 0.f ? x : 0.2f * x; }

__device__ __forceinline__ uint32_t f2tf32(float x) {
    uint32_t r; asm("cvt.rna.tf32.f32 %0, %1;" : "=r"(r) : "f"(x)); return r;
}

__device__ __forceinline__ void mma_tf32(float* d, const uint32_t* a, uint32_t b0, uint32_t b1) {
    asm volatile(
        "mma.sync.aligned.m16n8k8.row.col.f32.tf32.tf32.f32 "
        "{%0,%1,%2,%3}, {%4,%5,%6,%7}, {%8,%9}, {%0,%1,%2,%3};"
        : "+f"(d[0]), "+f"(d[1]), "+f"(d[2]), "+f"(d[3])
        : "r"(a[0]), "r"(a[1]), "r"(a[2]), "r"(a[3]), "r"(b0), "r"(b1));
}

// ---------------- CSR build ----------------
__global__ void zero_int_kernel(int* __restrict__ p, int n) {
    int i = blockIdx.x * blockDim.x + threadIdx.x;
    if (i < n) p[i] = 0;
}

__global__ void hist_kernel(const int* __restrict__ dst, int* __restrict__ deg, int e) {
    int i = blockIdx.x * blockDim.x + threadIdx.x;
    if (i < e) atomicAdd(&deg[dst[i]], 1);
}

__global__ void scan_kernel(const int* __restrict__ deg, int* __restrict__ off,
                            int* __restrict__ pos, int n) {
    __shared__ int sh[1024];
    int running = 0;
    for (int base = 0; base < n; base += 1024) {
        int i = base + threadIdx.x;
        int v = (i < n) ? deg[i] : 0;
        sh[threadIdx.x] = v;
        __syncthreads();
        for (int o = 1; o < 1024; o <<= 1) {
            int t = (threadIdx.x >= o) ? sh[threadIdx.x - o] : 0;
            __syncthreads();
            sh[threadIdx.x] += t;
            __syncthreads();
        }
        int excl = sh[threadIdx.x] - v;
        if (i < n) { off[i] = running + excl; pos[i] = running + excl; }
        running += sh[1023];
        __syncthreads();
    }
    if (threadIdx.x == 0) off[n] = running;
}

__global__ void scatter_kernel(const int* __restrict__ src, const int* __restrict__ dst,
                               int* __restrict__ pos, int* __restrict__ esrc, int e) {
    int i = blockIdx.x * blockDim.x + threadIdx.x;
    if (i < e) {
        int p = atomicAdd(&pos[dst[i]], 1);
        esrc[p] = src[i];
    }
}

// ---------------- single-pass TF32 mma GEMM (conflict-free smem) ----------
// Y[M,256] = X[M,K] @ W[K,256]. CTA tile 128m x 128n (grid.y = col half), BK=32.
// 512 threads = 16 warps in 4(m) x 4(n); warp tile 32x32 = 2 x 4 m16n8k8 tiles.
// smem: plain tf32 tiles, A stride 36 (bank = 4row+k), B stride 136 (bank = 8k+n):
// producer STS.128 and consumer fragment LDS.32 are both bank-conflict-free.
// EL: fused attention logits via smem partials (warp pairs share one head).
template <int K, bool EL>
__global__ void __launch_bounds__(512, 2) gemm_tc(
    const float* __restrict__ X, const float* __restrict__ W,
    float* __restrict__ Y,
    const float* __restrict__ al, const float* __restrict__ ar,
    float* __restrict__ el, float* __restrict__ er, int M)
{
    __shared__ uint32_t sA[128 * 36];   // [row][k]
    __shared__ uint32_t sB[32 * 136];   // [k][n]
    __shared__ float sal[128], sar[128];
    __shared__ float elp[16][32], erp[16][32];

    const int t    = threadIdx.x;
    const int wid  = t >> 5;
    const int lane = t & 31;
    const int wm   = wid & 3;
    const int wn   = wid >> 2;
    const int bm   = blockIdx.x * 128;
    const int bn   = blockIdx.y * 128;

    if (EL && t < 128) {
        sal[t] = al[bn + t];
        sar[t] = ar[bn + t];
    }

    float d[2][4][4];
    #pragma unroll
    for (int mi = 0; mi < 2; mi++)
        #pragma unroll
        for (int j = 0; j < 4; j++)
            #pragma unroll
            for (int q = 0; q < 4; q++) d[mi][j][q] = 0.f;

    const int NCH = K / 32;
    for (int c = 0; c < NCH; c++) {
        // ---- A tile: 128 rows x 32 k -> sA[row*36 + k], STS.128 ----
        #pragma unroll
        for (int l = 0; l < 2; l++) {
            int idx = t + l * 512;          // 0..1023 float4 slots
            int row = idx >> 3, f4 = idx & 7;
            int gr  = bm + row;
            float4 v = (gr < M) ? *(const float4*)(X + (size_t)gr * K + c * 32 + f4 * 4)
                                : make_float4(0.f, 0.f, 0.f, 0.f);
            uint4 u = make_uint4(f2tf32(v.x), f2tf32(v.y), f2tf32(v.z), f2tf32(v.w));
            *(uint4*)&sA[row * 36 + f4 * 4] = u;
        }
        // ---- B tile: 32 k x 128 n -> sB[k*136 + n], STS.128 ----
        #pragma unroll
        for (int l = 0; l < 2; l++) {
            int idx = t + l * 512;
            int kk = idx >> 5, nn4 = idx & 31;
            float4 v = *(const float4*)(W + (size_t)(c * 32 + kk) * 256 + bn + nn4 * 4);
            uint4 u = make_uint4(f2tf32(v.x), f2tf32(v.y), f2tf32(v.z), f2tf32(v.w));
            *(uint4*)&sB[kk * 136 + nn4 * 4] = u;
        }
        __syncthreads();

        // ---- consume: 4 k-steps of 8 ----
        #pragma unroll
        for (int s = 0; s < 4; s++) {
            const int k0 = s * 8 + (lane & 3);
            uint32_t a[2][4];
            #pragma unroll
            for (int mi = 0; mi < 2; mi++) {
                int rb_ = wm * 32 + mi * 16 + (lane >> 2);
                a[mi][0] = sA[rb_ * 36 + k0];
                a[mi][1] = sA[(rb_ + 8) * 36 + k0];
                a[mi][2] = sA[rb_ * 36 + k0 + 4];
                a[mi][3] = sA[(rb_ + 8) * 36 + k0 + 4];
            }
            #pragma unroll
            for (int j = 0; j < 4; j++) {
                int n = wn * 32 + j * 8 + (lane >> 2);
                uint32_t b0 = sB[k0 * 136 + n];
                uint32_t b1 = sB[(k0 + 4) * 136 + n];
                mma_tf32(d[0][j], a[0], b0, b1);
                mma_tf32(d[1][j], a[1], b0, b1);
            }
        }
        __syncthreads();
    }

    // ---- epilogue: write Y (+ fused el/er partials) ----
    float elA[2][2], erA[2][2];
    #pragma unroll
    for (int mi = 0; mi < 2; mi++) { elA[mi][0] = elA[mi][1] = 0.f; erA[mi][0] = erA[mi][1] = 0.f; }

    #pragma unroll
    for (int mi = 0; mi < 2; mi++) {
        int r0 = bm + wm * 32 + mi * 16 + (lane >> 2);
        #pragma unroll
        for (int j = 0; j < 4; j++) {
            int cl = wn * 32 + j * 8 + (lane & 3) * 2;   // col within 128-block
            int cb = bn + cl;
            if (r0 < M)
                *(float2*)(Y + (size_t)r0 * 256 + cb) = make_float2(d[mi][j][0], d[mi][j][1]);
            if (r0 + 8 < M)
                *(float2*)(Y + (size_t)(r0 + 8) * 256 + cb) = make_float2(d[mi][j][2], d[mi][j][3]);
            if (EL) {
                float a0 = sal[cl], a1 = sal[cl + 1];
                float q0 = sar[cl], q1 = sar[cl + 1];
                elA[mi][0] = fmaf(d[mi][j][0], a0, fmaf(d[mi][j][1], a1, elA[mi][0]));
                elA[mi][1] = fmaf(d[mi][j][2], a0, fmaf(d[mi][j][3], a1, elA[mi][1]));
                erA[mi][0] = fmaf(d[mi][j][0], q0, fmaf(d[mi][j][1], q1, erA[mi][0]));
                erA[mi][1] = fmaf(d[mi][j][2], q0, fmaf(d[mi][j][3], q1, erA[mi][1]));
            }
        }
    }

    if (EL) {
        #pragma unroll
        for (int mi = 0; mi < 2; mi++) {
            #pragma unroll
            for (int hrow = 0; hrow < 2; hrow++) {
                float vl = elA[mi][hrow], vr = erA[mi][hrow];
                vl += __shfl_xor_sync(0xffffffffu, vl, 1);
                vl += __shfl_xor_sync(0xffffffffu, vl, 2);
                vr += __shfl_xor_sync(0xffffffffu, vr, 1);
                vr += __shfl_xor_sync(0xffffffffu, vr, 2);
                if ((lane & 3) == 0) {
                    int rl = mi * 16 + (lane >> 2) + hrow * 8;   // 0..31
                    elp[wid][rl] = vl;
                    erp[wid][rl] = vr;
                }
            }
        }
        __syncthreads();
        // combine warp pairs: head h sums wn = 2h and 2h+1 (same rows per wm)
        int q = t;
        if (q < 256) {
            int hh = q >> 7, wm2 = (q >> 5) & 3, rl = q & 31;
            int row = bm + wm2 * 32 + rl;
            if (row < M)
                el[row * 4 + blockIdx.y * 2 + hh] =
                    elp[(hh * 2) * 4 + wm2][rl] + elp[(hh * 2 + 1) * 4 + wm2][rl];
        } else {
            q -= 256;
            int hh = q >> 7, wm2 = (q >> 5) & 3, rl = q & 31;
            int row = bm + wm2 * 32 + rl;
            if (row < M)
                er[row * 4 + blockIdx.y * 2 + hh] =
                    erp[(hh * 2) * 4 + wm2][rl] + erp[(hh * 2 + 1) * 4 + wm2][rl];
        }
    }
}

// ---------------- per-destination softmax aggregation ----------------
template <int MODE>  // 0: relu, write [N,256] ; 1: final, head-mean -> [N,64]
__global__ void __launch_bounds__(256) agg_kernel(
    const int* __restrict__ off, const int* __restrict__ esrc,
    const float* __restrict__ el, const float* __restrict__ er,
    const float* __restrict__ ft, const float* __restrict__ resid,
    float* __restrict__ out, int n)
{
    const int t    = threadIdx.x;
    const int warp = t >> 5;
    const int lane = t & 31;
    const int nl   = warp >> 1;
    const int half = warp & 1;
    const int nid  = blockIdx.x * 4 + nl;
    const bool active = (nid < n);

    __shared__ float4 smA[4][16];
    __shared__ float4 smB[4][16];

    float v0 = 0.f, v1 = 0.f, v2 = 0.f, v3 = 0.f;

    if (active) {
        const int s = off[nid], eEnd = off[nid + 1];
        float2 erp = *(const float2*)(er + nid * 4 + half * 2);

        float mxa = -1e30f, mxb = -1e30f;
        for (int i = s + lane; i < eEnd; i += 32) {
            int sc = esrc[i];
            float2 ep = *(const float2*)(el + sc * 4 + half * 2);
            mxa = fmaxf(mxa, lrelu(ep.x + erp.x));
            mxb = fmaxf(mxb, lrelu(ep.y + erp.y));
        }
        #pragma unroll
        for (int o = 16; o; o >>= 1) {
            mxa = fmaxf(mxa, __shfl_xor_sync(0xffffffffu, mxa, o));
            mxb = fmaxf(mxb, __shfl_xor_sync(0xffffffffu, mxb, o));
        }

        const float m_h  = (lane < 16) ? mxa : mxb;
        const float er_h = (lane < 16) ? erp.x : erp.y;
        const int   hOff = half * 2 + (lane >> 4);
        const int   fidx = half * 32 + lane;

        float den = 0.f;
        float a0 = 0.f, a1 = 0.f, a2 = 0.f, a3 = 0.f;
        const float4* ft4 = (const float4*)ft;

        int i = s;
        for (; i + 3 < eEnd; i += 4) {
            int sc0 = __ldg(esrc + i);
            int sc1 = __ldg(esrc + i + 1);
            int sc2 = __ldg(esrc + i + 2);
            int sc3 = __ldg(esrc + i + 3);
            float e0 = __ldg(el + sc0 * 4 + hOff);
            float e1 = __ldg(el + sc1 * 4 + hOff);
            float e2 = __ldg(el + sc2 * 4 + hOff);
            float e3 = __ldg(el + sc3 * 4 + hOff);
            float4 f0 = ft4[(size_t)sc0 * 64 + fidx];
            float4 f1 = ft4[(size_t)sc1 * 64 + fidx];
            float4 f2 = ft4[(size_t)sc2 * 64 + fidx];
            float4 f3 = ft4[(size_t)sc3 * 64 + fidx];
            float x0 = __expf(lrelu(e0 + er_h) - m_h);
            float x1 = __expf(lrelu(e1 + er_h) - m_h);
            float x2 = __expf(lrelu(e2 + er_h) - m_h);
            float x3 = __expf(lrelu(e3 + er_h) - m_h);
            den += (x0 + x1) + (x2 + x3);
            a0 = fmaf(x0, f0.x, a0); a1 = fmaf(x0, f0.y, a1);
            a2 = fmaf(x0, f0.z, a2); a3 = fmaf(x0, f0.w, a3);
            a0 = fmaf(x1, f1.x, a0); a1 = fmaf(x1, f1.y, a1);
            a2 = fmaf(x1, f1.z, a2); a3 = fmaf(x1, f1.w, a3);
            a0 = fmaf(x2, f2.x, a0); a1 = fmaf(x2, f2.y, a1);
            a2 = fmaf(x2, f2.z, a2); a3 = fmaf(x2, f2.w, a3);
            a0 = fmaf(x3, f3.x, a0); a1 = fmaf(x3, f3.y, a1);
            a2 = fmaf(x3, f3.z, a2); a3 = fmaf(x3, f3.w, a3);
        }
        for (; i < eEnd; i++) {
            int sc = __ldg(esrc + i);
            float ev = lrelu(__ldg(el + sc * 4 + hOff) + er_h);
            float ex = __expf(ev - m_h);
            den += ex;
            float4 f = ft4[(size_t)sc * 64 + fidx];
            a0 = fmaf(ex, f.x, a0); a1 = fmaf(ex, f.y, a1);
            a2 = fmaf(ex, f.z, a2); a3 = fmaf(ex, f.w, a3);
        }

        float inv = (eEnd > s) ? (1.0f / den) : 0.f;
        float4 r = *(const float4*)(resid + (size_t)nid * FDIM + half * 128 + lane * 4);
        v0 = fmaf(a0, inv, r.x);
        v1 = fmaf(a1, inv, r.y);
        v2 = fmaf(a2, inv, r.z);
        v3 = fmaf(a3, inv, r.w);
    }

    if (MODE == 0) {
        if (active) {
            v0 = fmaxf(v0, 0.f); v1 = fmaxf(v1, 0.f);
            v2 = fmaxf(v2, 0.f); v3 = fmaxf(v3, 0.f);
            *(float4*)(out + (size_t)nid * FDIM + half * 128 + lane * 4) =
                make_float4(v0, v1, v2, v3);
        }
    } else {
        v0 += __shfl_xor_sync(0xffffffffu, v0, 16);
        v1 += __shfl_xor_sync(0xffffffffu, v1, 16);
        v2 += __shfl_xor_sync(0xffffffffu, v2, 16);
        v3 += __shfl_xor_sync(0xffffffffu, v3, 16);
        if (lane < 16) {
            if (half) smB[nl][lane] = make_float4(v0, v1, v2, v3);
            else      smA[nl][lane] = make_float4(v0, v1, v2, v3);
        }
        __syncthreads();
        if (half == 0 && lane < 16 && active) {
            float4 a = smA[nl][lane], b = smB[nl][lane];
            *(float4*)(out + (size_t)nid * 64 + lane * 4) =
                make_float4((a.x + b.x) * 0.25f, (a.y + b.y) * 0.25f,
                            (a.z + b.z) * 0.25f, (a.w + b.w) * 0.25f);
        }
    }
}

// ---------------- edge scoring MLP as register-tiled GEMM ----------------
__global__ void __launch_bounds__(256) mlp_kernel(
    const float* __restrict__ hf, const int* __restrict__ src,
    const int* __restrict__ dst, const float* __restrict__ Wm1,
    const float* __restrict__ bm1, const float* __restrict__ Wm2,
    const float* __restrict__ bm2, float* __restrict__ out, int e)
{
    __shared__ float sD[64][68];
    __shared__ float sW[64][64];
    __shared__ float sb[64];
    __shared__ float sW2[64];

    const int t    = threadIdx.x;
    const int warp = t >> 5;
    const int lane = t & 31;
    const int e0   = blockIdx.x * 64;

    for (int i = t; i < 64 * 64; i += 256) sW[i >> 6][i & 63] = Wm1[i];
    if (t < 64) { sb[t] = bm1[t]; sW2[t] = Wm2[t]; }

    #pragma unroll
    for (int j = 0; j < 8; j++) {
        int le  = warp * 8 + j;
        int eid = e0 + le;
        float2 dv;
        if (eid < e) {
            int s = src[eid], d = dst[eid];
            float2 a = *(const float2*)(hf + (size_t)s * 64 + lane * 2);
            float2 b = *(const float2*)(hf + (size_t)d * 64 + lane * 2);
            dv.x = fabsf(a.x - b.x);
            dv.y = fabsf(a.y - b.y);
        } else {
            dv.x = 0.f; dv.y = 0.f;
        }
        *(float2*)&sD[le][lane * 2] = dv;
    }
    __syncthreads();

    const int tx = t & 15;
    const int ty = t >> 4;

    float z[4][4];
    #pragma unroll
    for (int i = 0; i < 4; i++)
        #pragma unroll
        for (int j = 0; j < 4; j++) z[i][j] = sb[tx * 4 + j];

    #pragma unroll 8
    for (int k = 0; k < 64; k++) {
        float4 wv = *(const float4*)&sW[k][tx * 4];
        float d0 = sD[ty * 4 + 0][k];
        float d1 = sD[ty * 4 + 1][k];
        float d2 = sD[ty * 4 + 2][k];
        float d3 = sD[ty * 4 + 3][k];
        z[0][0] = fmaf(d0, wv.x, z[0][0]); z[0][1] = fmaf(d0, wv.y, z[0][1]);
        z[0][2] = fmaf(d0, wv.z, z[0][2]); z[0][3] = fmaf(d0, wv.w, z[0][3]);
        z[1][0] = fmaf(d1, wv.x, z[1][0]); z[1][1] = fmaf(d1, wv.y, z[1][1]);
        z[1][2] = fmaf(d1, wv.z, z[1][2]); z[1][3] = fmaf(d1, wv.w, z[1][3]);
        z[2][0] = fmaf(d2, wv.x, z[2][0]); z[2][1] = fmaf(d2, wv.y, z[2][1]);
        z[2][2] = fmaf(d2, wv.z, z[2][2]); z[2][3] = fmaf(d2, wv.w, z[2][3]);
        z[3][0] = fmaf(d3, wv.x, z[3][0]); z[3][1] = fmaf(d3, wv.y, z[3][1]);
        z[3][2] = fmaf(d3, wv.z, z[3][2]); z[3][3] = fmaf(d3, wv.w, z[3][3]);
    }

    float w2a = sW2[tx * 4 + 0], w2b = sW2[tx * 4 + 1];
    float w2c = sW2[tx * 4 + 2], w2d = sW2[tx * 4 + 3];
    float p[4];
    #pragma unroll
    for (int i = 0; i < 4; i++) {
        p[i] = fmaxf(z[i][0], 0.f) * w2a + fmaxf(z[i][1], 0.f) * w2b
             + fmaxf(z[i][2], 0.f) * w2c + fmaxf(z[i][3], 0.f) * w2d;
        #pragma unroll
        for (int o = 8; o; o >>= 1) p[i] += __shfl_xor_sync(0xffffffffu, p[i], o);
    }
    if (tx == 0) {
        float b2 = bm2[0];
        #pragma unroll
        for (int i = 0; i < 4; i++) {
            int eid = e0 + ty * 4 + i;
            if (eid < e) out[eid] = 1.0f / (1.0f + __expf(-(p[i] + b2)));
        }
    }
}

// ---------------- launch ----------------
extern "C" void kernel_launch(void* const* d_in, const int* in_sizes, int n_in,
                              void* d_out, int out_size)
{
    const float* h   = (const float*)d_in[0];
    const int*   src = (const int*)d_in[1];
    const int*   dst = (const int*)d_in[2];
    const float* W1  = (const float*)d_in[3];
    const float* Wr1 = (const float*)d_in[4];
    const float* al1 = (const float*)d_in[5];
    const float* ar1 = (const float*)d_in[6];
    const float* W2  = (const float*)d_in[7];
    const float* al2 = (const float*)d_in[8];
    const float* ar2 = (const float*)d_in[9];
    const float* W3  = (const float*)d_in[10];
    const float* al3 = (const float*)d_in[11];
    const float* ar3 = (const float*)d_in[12];
    const float* Wm1 = (const float*)d_in[13];
    const float* bm1 = (const float*)d_in[14];
    const float* Wm2 = (const float*)d_in[15];
    const float* bm2 = (const float*)d_in[16];
    float* out = (float*)d_out;

    const int n = in_sizes[0] / 128;   // 50000
    const int e = in_sizes[1];         // 800000

    float *ft, *x, *res, *el, *er, *hfp;
    int *deg, *off, *pos, *esrc;
    cudaGetSymbolAddress((void**)&ft,   g_ft);
    cudaGetSymbolAddress((void**)&x,    g_x);
    cudaGetSymbolAddress((void**)&res,  g_res);
    cudaGetSymbolAddress((void**)&el,   g_el);
    cudaGetSymbolAddress((void**)&er,   g_er);
    cudaGetSymbolAddress((void**)&hfp,  g_hf);
    cudaGetSymbolAddress((void**)&deg,  g_deg);
    cudaGetSymbolAddress((void**)&off,  g_off);
    cudaGetSymbolAddress((void**)&pos,  g_pos);
    cudaGetSymbolAddress((void**)&esrc, g_esrc);

    dim3 gg((n + 127) / 128, 2);
    const int ga = (n + 3) / 4;

    // CSR prefix first, then layer-1 GEMM in the ncu-profiled slot,
    // then scatter (must precede agg; stream order guarantees it).
    zero_int_kernel<<<(n + 1 + 255) / 256, 256>>>(deg, n + 1);
    hist_kernel<<<(e + 255) / 256, 256>>>(dst, deg, e);
    scan_kernel<<<1, 1024>>>(deg, off, pos, n);

    gemm_tc<128, true ><<<gg, 512>>>(h, W1,  ft,  al1, ar1, el, er, n);   // profiled slot
    gemm_tc<128, false><<<gg, 512>>>(h, Wr1, res, nullptr, nullptr, nullptr, nullptr, n);

    scatter_kernel<<<(e + 255) / 256, 256>>>(src, dst, pos, esrc, e);

    agg_kernel<0><<<ga, 256>>>(off, esrc, el, er, ft, res, x, n);
    // Layer 2 (identity residual)
    gemm_tc<256, true><<<gg, 512>>>(x, W2, ft, al2, ar2, el, er, n);
    agg_kernel<0><<<ga, 256>>>(off, esrc, el, er, ft, x, x, n);
    // Layer 3 (identity residual, no activation, head-mean -> hf)
    gemm_tc<256, true><<<gg, 512>>>(x, W3, ft, al3, ar3, el, er, n);
    agg_kernel<1><<<ga, 256>>>(off, esrc, el, er, ft, x, hfp, n);

    // Edge MLP -> scores
    mlp_kernel<<<(e + 63) / 64, 256>>>(hfp, src, dst, Wm1, bm1, Wm2, bm2, out, e);
}

// round 10
// speedup vs baseline: 2.0891x; 1.1287x over previous
#include <cuda_runtime.h>
#include <math.h>
#include <stdint.h>

#define NN 50000
#define EE 800000
#define FDIM 256   /* HEADS*HID */

// ---------------- scratch (device globals: allowed) ----------------
__device__ float g_ft[(size_t)NN * FDIM];
__device__ float g_x [(size_t)NN * FDIM];
__device__ float g_res[(size_t)NN * FDIM];
__device__ float g_el[NN * 4];
__device__ float g_er[NN * 4];
__device__ float g_hf[NN * 64];
__device__ int   g_deg[NN + 1];
__device__ int   g_off[NN + 1];
__device__ int   g_pos[NN];
__device__ int   g_esrc[EE];

__device__ __forceinline__ float lrelu(float x) { return x > 0.f ? x : 0.2f * x; }

__device__ __forceinline__ uint32_t f2tf32(float x) {
    uint32_t r; asm("cvt.rna.tf32.f32 %0, %1;" : "=r"(r) : "f"(x)); return r;
}

__device__ __forceinline__ void mma_tf32(float* d, const uint32_t* a, uint32_t b0, uint32_t b1) {
    asm volatile(
        "mma.sync.aligned.m16n8k8.row.col.f32.tf32.tf32.f32 "
        "{%0,%1,%2,%3}, {%4,%5,%6,%7}, {%8,%9}, {%0,%1,%2,%3};"
        : "+f"(d[0]), "+f"(d[1]), "+f"(d[2]), "+f"(d[3])
        : "r"(a[0]), "r"(a[1]), "r"(a[2]), "r"(a[3]), "r"(b0), "r"(b1));
}

// ---------------- CSR build ----------------
__global__ void zero_int_kernel(int* __restrict__ p, int n) {
    int i = blockIdx.x * blockDim.x + threadIdx.x;
    if (i < n) p[i] = 0;
}

__global__ void hist_kernel(const int* __restrict__ dst, int* __restrict__ deg, int e) {
    int i = blockIdx.x * blockDim.x + threadIdx.x;
    if (i < e) atomicAdd(&deg[dst[i]], 1);
}

__global__ void scan_kernel(const int* __restrict__ deg, int* __restrict__ off,
                            int* __restrict__ pos, int n) {
    __shared__ int sh[1024];
    int running = 0;
    for (int base = 0; base < n; base += 1024) {
        int i = base + threadIdx.x;
        int v = (i < n) ? deg[i] : 0;
        sh[threadIdx.x] = v;
        __syncthreads();
        for (int o = 1; o < 1024; o <<= 1) {
            int t = (threadIdx.x >= o) ? sh[threadIdx.x - o] : 0;
            __syncthreads();
            sh[threadIdx.x] += t;
            __syncthreads();
        }
        int excl = sh[threadIdx.x] - v;
        if (i < n) { off[i] = running + excl; pos[i] = running + excl; }
        running += sh[1023];
        __syncthreads();
    }
    if (threadIdx.x == 0) off[n] = running;
}

__global__ void scatter_kernel(const int* __restrict__ src, const int* __restrict__ dst,
                               int* __restrict__ pos, int* __restrict__ esrc, int e) {
    int i = blockIdx.x * blockDim.x + threadIdx.x;
    if (i < e) {
        int p = atomicAdd(&pos[dst[i]], 1);
        esrc[p] = src[i];
    }
}

// ---------------- single-pass TF32 mma GEMM (conflict-free smem) ----------
template <int K, bool EL>
__global__ void __launch_bounds__(512, 2) gemm_tc(
    const float* __restrict__ X, const float* __restrict__ W,
    float* __restrict__ Y,
    const float* __restrict__ al, const float* __restrict__ ar,
    float* __restrict__ el, float* __restrict__ er, int M)
{
    __shared__ uint32_t sA[128 * 36];   // [row][k]
    __shared__ uint32_t sB[32 * 136];   // [k][n]
    __shared__ float sal[128], sar[128];
    __shared__ float elp[16][32], erp[16][32];

    const int t    = threadIdx.x;
    const int wid  = t >> 5;
    const int lane = t & 31;
    const int wm   = wid & 3;
    const int wn   = wid >> 2;
    const int bm   = blockIdx.x * 128;
    const int bn   = blockIdx.y * 128;

    if (EL && t < 128) {
        sal[t] = al[bn + t];
        sar[t] = ar[bn + t];
    }

    float d[2][4][4];
    #pragma unroll
    for (int mi = 0; mi < 2; mi++)
        #pragma unroll
        for (int j = 0; j < 4; j++)
            #pragma unroll
            for (int q = 0; q < 4; q++) d[mi][j][q] = 0.f;

    const int NCH = K / 32;
    for (int c = 0; c < NCH; c++) {
        #pragma unroll
        for (int l = 0; l < 2; l++) {
            int idx = t + l * 512;
            int row = idx >> 3, f4 = idx & 7;
            int gr  = bm + row;
            float4 v = (gr < M) ? *(const float4*)(X + (size_t)gr * K + c * 32 + f4 * 4)
                                : make_float4(0.f, 0.f, 0.f, 0.f);
            uint4 u = make_uint4(f2tf32(v.x), f2tf32(v.y), f2tf32(v.z), f2tf32(v.w));
            *(uint4*)&sA[row * 36 + f4 * 4] = u;
        }
        #pragma unroll
        for (int l = 0; l < 2; l++) {
            int idx = t + l * 512;
            int kk = idx >> 5, nn4 = idx & 31;
            float4 v = *(const float4*)(W + (size_t)(c * 32 + kk) * 256 + bn + nn4 * 4);
            uint4 u = make_uint4(f2tf32(v.x), f2tf32(v.y), f2tf32(v.z), f2tf32(v.w));
            *(uint4*)&sB[kk * 136 + nn4 * 4] = u;
        }
        __syncthreads();

        #pragma unroll
        for (int s = 0; s < 4; s++) {
            const int k0 = s * 8 + (lane & 3);
            uint32_t a[2][4];
            #pragma unroll
            for (int mi = 0; mi < 2; mi++) {
                int rb_ = wm * 32 + mi * 16 + (lane >> 2);
                a[mi][0] = sA[rb_ * 36 + k0];
                a[mi][1] = sA[(rb_ + 8) * 36 + k0];
                a[mi][2] = sA[rb_ * 36 + k0 + 4];
                a[mi][3] = sA[(rb_ + 8) * 36 + k0 + 4];
            }
            #pragma unroll
            for (int j = 0; j < 4; j++) {
                int n = wn * 32 + j * 8 + (lane >> 2);
                uint32_t b0 = sB[k0 * 136 + n];
                uint32_t b1 = sB[(k0 + 4) * 136 + n];
                mma_tf32(d[0][j], a[0], b0, b1);
                mma_tf32(d[1][j], a[1], b0, b1);
            }
        }
        __syncthreads();
    }

    float elA[2][2], erA[2][2];
    #pragma unroll
    for (int mi = 0; mi < 2; mi++) { elA[mi][0] = elA[mi][1] = 0.f; erA[mi][0] = erA[mi][1] = 0.f; }

    #pragma unroll
    for (int mi = 0; mi < 2; mi++) {
        int r0 = bm + wm * 32 + mi * 16 + (lane >> 2);
        #pragma unroll
        for (int j = 0; j < 4; j++) {
            int cl = wn * 32 + j * 8 + (lane & 3) * 2;
            int cb = bn + cl;
            if (r0 < M)
                *(float2*)(Y + (size_t)r0 * 256 + cb) = make_float2(d[mi][j][0], d[mi][j][1]);
            if (r0 + 8 < M)
                *(float2*)(Y + (size_t)(r0 + 8) * 256 + cb) = make_float2(d[mi][j][2], d[mi][j][3]);
            if (EL) {
                float a0 = sal[cl], a1 = sal[cl + 1];
                float q0 = sar[cl], q1 = sar[cl + 1];
                elA[mi][0] = fmaf(d[mi][j][0], a0, fmaf(d[mi][j][1], a1, elA[mi][0]));
                elA[mi][1] = fmaf(d[mi][j][2], a0, fmaf(d[mi][j][3], a1, elA[mi][1]));
                erA[mi][0] = fmaf(d[mi][j][0], q0, fmaf(d[mi][j][1], q1, erA[mi][0]));
                erA[mi][1] = fmaf(d[mi][j][2], q0, fmaf(d[mi][j][3], q1, erA[mi][1]));
            }
        }
    }

    if (EL) {
        #pragma unroll
        for (int mi = 0; mi < 2; mi++) {
            #pragma unroll
            for (int hrow = 0; hrow < 2; hrow++) {
                float vl = elA[mi][hrow], vr = erA[mi][hrow];
                vl += __shfl_xor_sync(0xffffffffu, vl, 1);
                vl += __shfl_xor_sync(0xffffffffu, vl, 2);
                vr += __shfl_xor_sync(0xffffffffu, vr, 1);
                vr += __shfl_xor_sync(0xffffffffu, vr, 2);
                if ((lane & 3) == 0) {
                    int rl = mi * 16 + (lane >> 2) + hrow * 8;
                    elp[wid][rl] = vl;
                    erp[wid][rl] = vr;
                }
            }
        }
        __syncthreads();
        int q = t;
        if (q < 256) {
            int hh = q >> 7, wm2 = (q >> 5) & 3, rl = q & 31;
            int row = bm + wm2 * 32 + rl;
            if (row < M)
                el[row * 4 + blockIdx.y * 2 + hh] =
                    elp[(hh * 2) * 4 + wm2][rl] + elp[(hh * 2 + 1) * 4 + wm2][rl];
        } else {
            q -= 256;
            int hh = q >> 7, wm2 = (q >> 5) & 3, rl = q & 31;
            int row = bm + wm2 * 32 + rl;
            if (row < M)
                er[row * 4 + blockIdx.y * 2 + hh] =
                    erp[(hh * 2) * 4 + wm2][rl] + erp[(hh * 2 + 1) * 4 + wm2][rl];
        }
    }
}

// ---------------- per-destination softmax aggregation ----------------
template <int MODE>  // 0: relu, write [N,256] ; 1: final, head-mean -> [N,64]
__global__ void __launch_bounds__(256) agg_kernel(
    const int* __restrict__ off, const int* __restrict__ esrc,
    const float* __restrict__ el, const float* __restrict__ er,
    const float* __restrict__ ft, const float* __restrict__ resid,
    float* __restrict__ out, int n)
{
    const int t    = threadIdx.x;
    const int warp = t >> 5;
    const int lane = t & 31;
    const int nl   = warp >> 1;
    const int half = warp & 1;
    const int nid  = blockIdx.x * 4 + nl;
    const bool active = (nid < n);

    __shared__ float4 smA[4][16];
    __shared__ float4 smB[4][16];

    float v0 = 0.f, v1 = 0.f, v2 = 0.f, v3 = 0.f;

    if (active) {
        const int s = off[nid], eEnd = off[nid + 1];
        float2 erp = *(const float2*)(er + nid * 4 + half * 2);

        float mxa = -1e30f, mxb = -1e30f;
        for (int i = s + lane; i < eEnd; i += 32) {
            int sc = esrc[i];
            float2 ep = *(const float2*)(el + sc * 4 + half * 2);
            mxa = fmaxf(mxa, lrelu(ep.x + erp.x));
            mxb = fmaxf(mxb, lrelu(ep.y + erp.y));
        }
        #pragma unroll
        for (int o = 16; o; o >>= 1) {
            mxa = fmaxf(mxa, __shfl_xor_sync(0xffffffffu, mxa, o));
            mxb = fmaxf(mxb, __shfl_xor_sync(0xffffffffu, mxb, o));
        }

        const float m_h  = (lane < 16) ? mxa : mxb;
        const float er_h = (lane < 16) ? erp.x : erp.y;
        const int   hOff = half * 2 + (lane >> 4);
        const int   fidx = half * 32 + lane;

        float den = 0.f;
        float a0 = 0.f, a1 = 0.f, a2 = 0.f, a3 = 0.f;
        const float4* ft4 = (const float4*)ft;

        int i = s;
        for (; i + 3 < eEnd; i += 4) {
            int sc0 = __ldg(esrc + i);
            int sc1 = __ldg(esrc + i + 1);
            int sc2 = __ldg(esrc + i + 2);
            int sc3 = __ldg(esrc + i + 3);
            float e0 = __ldg(el + sc0 * 4 + hOff);
            float e1 = __ldg(el + sc1 * 4 + hOff);
            float e2 = __ldg(el + sc2 * 4 + hOff);
            float e3 = __ldg(el + sc3 * 4 + hOff);
            float4 f0 = ft4[(size_t)sc0 * 64 + fidx];
            float4 f1 = ft4[(size_t)sc1 * 64 + fidx];
            float4 f2 = ft4[(size_t)sc2 * 64 + fidx];
            float4 f3 = ft4[(size_t)sc3 * 64 + fidx];
            float x0 = __expf(lrelu(e0 + er_h) - m_h);
            float x1 = __expf(lrelu(e1 + er_h) - m_h);
            float x2 = __expf(lrelu(e2 + er_h) - m_h);
            float x3 = __expf(lrelu(e3 + er_h) - m_h);
            den += (x0 + x1) + (x2 + x3);
            a0 = fmaf(x0, f0.x, a0); a1 = fmaf(x0, f0.y, a1);
            a2 = fmaf(x0, f0.z, a2); a3 = fmaf(x0, f0.w, a3);
            a0 = fmaf(x1, f1.x, a0); a1 = fmaf(x1, f1.y, a1);
            a2 = fmaf(x1, f1.z, a2); a3 = fmaf(x1, f1.w, a3);
            a0 = fmaf(x2, f2.x, a0); a1 = fmaf(x2, f2.y, a1);
            a2 = fmaf(x2, f2.z, a2); a3 = fmaf(x2, f2.w, a3);
            a0 = fmaf(x3, f3.x, a0); a1 = fmaf(x3, f3.y, a1);
            a2 = fmaf(x3, f3.z, a2); a3 = fmaf(x3, f3.w, a3);
        }
        for (; i < eEnd; i++) {
            int sc = __ldg(esrc + i);
            float ev = lrelu(__ldg(el + sc * 4 + hOff) + er_h);
            float ex = __expf(ev - m_h);
            den += ex;
            float4 f = ft4[(size_t)sc * 64 + fidx];
            a0 = fmaf(ex, f.x, a0); a1 = fmaf(ex, f.y, a1);
            a2 = fmaf(ex, f.z, a2); a3 = fmaf(ex, f.w, a3);
        }

        float inv = (eEnd > s) ? (1.0f / den) : 0.f;
        float4 r = *(const float4*)(resid + (size_t)nid * FDIM + half * 128 + lane * 4);
        v0 = fmaf(a0, inv, r.x);
        v1 = fmaf(a1, inv, r.y);
        v2 = fmaf(a2, inv, r.z);
        v3 = fmaf(a3, inv, r.w);
    }

    if (MODE == 0) {
        if (active) {
            v0 = fmaxf(v0, 0.f); v1 = fmaxf(v1, 0.f);
            v2 = fmaxf(v2, 0.f); v3 = fmaxf(v3, 0.f);
            *(float4*)(out + (size_t)nid * FDIM + half * 128 + lane * 4) =
                make_float4(v0, v1, v2, v3);
        }
    } else {
        v0 += __shfl_xor_sync(0xffffffffu, v0, 16);
        v1 += __shfl_xor_sync(0xffffffffu, v1, 16);
        v2 += __shfl_xor_sync(0xffffffffu, v2, 16);
        v3 += __shfl_xor_sync(0xffffffffu, v3, 16);
        if (lane < 16) {
            if (half) smB[nl][lane] = make_float4(v0, v1, v2, v3);
            else      smA[nl][lane] = make_float4(v0, v1, v2, v3);
        }
        __syncthreads();
        if (half == 0 && lane < 16 && active) {
            float4 a = smA[nl][lane], b = smB[nl][lane];
            *(float4*)(out + (size_t)nid * 64 + lane * 4) =
                make_float4((a.x + b.x) * 0.25f, (a.y + b.y) * 0.25f,
                            (a.z + b.z) * 0.25f, (a.w + b.w) * 0.25f);
        }
    }
}

// ---------------- edge scoring MLP via TF32 mma ----------------
// Per block: 64 edges. z[64x64] = |hf[src]-hf[dst]| @ Wm1; relu; dot Wm2; sigmoid.
// Fragment layouts identical (bank-verified) to gemm_tc: A stride 68, B stride 72.
// 8 warps = 2(m) x 4(n); warp tile 32x16 = 2x2 m16n8k8 tiles; K=64 (8 ksteps).
__global__ void __launch_bounds__(256) mlp_tc_kernel(
    const float* __restrict__ hf, const int* __restrict__ src,
    const int* __restrict__ dst, const float* __restrict__ Wm1,
    const float* __restrict__ bm1, const float* __restrict__ Wm2,
    const float* __restrict__ bm2, float* __restrict__ out, int e)
{
    __shared__ uint32_t sD[64 * 68];   // [edge][k] tf32
    __shared__ uint32_t sW[64 * 72];   // [k][n]   tf32
    __shared__ float sb[64], sW2[64];
    __shared__ float part[4][64];      // [wn][edge]

    const int t    = threadIdx.x;
    const int wid  = t >> 5;
    const int lane = t & 31;
    const int wm   = wid & 1;    // 2 m-warps
    const int wn   = wid >> 1;   // 4 n-warps
    const int e0   = blockIdx.x * 64;

    for (int i = t; i < 64 * 64; i += 256)
        sW[(i >> 6) * 72 + (i & 63)] = f2tf32(Wm1[i]);
    if (t < 64) { sb[t] = bm1[t]; sW2[t] = Wm2[t]; }

    // build |hf[s]-hf[d]| rows (warp wid -> edges e0+wid*8 .. +8), tf32
    #pragma unroll
    for (int j = 0; j < 8; j++) {
        int le  = wid * 8 + j;
        int eid = e0 + le;
        float2 dv = make_float2(0.f, 0.f);
        if (eid < e) {
            int s = src[eid], d = dst[eid];
            float2 a = *(const float2*)(hf + (size_t)s * 64 + lane * 2);
            float2 b = *(const float2*)(hf + (size_t)d * 64 + lane * 2);
            dv.x = fabsf(a.x - b.x);
            dv.y = fabsf(a.y - b.y);
        }
        uint2 u = make_uint2(f2tf32(dv.x), f2tf32(dv.y));
        *(uint2*)&sD[le * 68 + lane * 2] = u;
    }
    __syncthreads();

    float d[2][2][4];
    #pragma unroll
    for (int mi = 0; mi < 2; mi++)
        #pragma unroll
        for (int j = 0; j < 2; j++)
            #pragma unroll
            for (int q = 0; q < 4; q++) d[mi][j][q] = 0.f;

    #pragma unroll
    for (int s = 0; s < 8; s++) {
        const int k0 = s * 8 + (lane & 3);
        uint32_t a[2][4];
        #pragma unroll
        for (int mi = 0; mi < 2; mi++) {
            int rb = wm * 32 + mi * 16 + (lane >> 2);
            a[mi][0] = sD[rb * 68 + k0];
            a[mi][1] = sD[(rb + 8) * 68 + k0];
            a[mi][2] = sD[rb * 68 + k0 + 4];
            a[mi][3] = sD[(rb + 8) * 68 + k0 + 4];
        }
        #pragma unroll
        for (int j = 0; j < 2; j++) {
            int n = wn * 16 + j * 8 + (lane >> 2);
            uint32_t b0 = sW[k0 * 72 + n];
            uint32_t b1 = sW[(k0 + 4) * 72 + n];
            mma_tf32(d[0][j], a[0], b0, b1);
            mma_tf32(d[1][j], a[1], b0, b1);
        }
    }

    // epilogue: bias + relu + Wm2 dot; quad shuffle-reduce; cross-warp via smem
    #pragma unroll
    for (int mi = 0; mi < 2; mi++) {
        float pA = 0.f, pB = 0.f;   // rows r0 and r0+8
        #pragma unroll
        for (int j = 0; j < 2; j++) {
            int c0 = wn * 16 + j * 8 + (lane & 3) * 2;
            float w0 = sW2[c0], w1 = sW2[c0 + 1];
            float b0 = sb[c0],  b1 = sb[c0 + 1];
            pA += fmaxf(d[mi][j][0] + b0, 0.f) * w0 + fmaxf(d[mi][j][1] + b1, 0.f) * w1;
            pB += fmaxf(d[mi][j][2] + b0, 0.f) * w0 + fmaxf(d[mi][j][3] + b1, 0.f) * w1;
        }
        pA += __shfl_xor_sync(0xffffffffu, pA, 1);
        pA += __shfl_xor_sync(0xffffffffu, pA, 2);
        pB += __shfl_xor_sync(0xffffffffu, pB, 1);
        pB += __shfl_xor_sync(0xffffffffu, pB, 2);
        if ((lane & 3) == 0) {
            int rl = wm * 32 + mi * 16 + (lane >> 2);
            part[wn][rl]     = pA;
            part[wn][rl + 8] = pB;
        }
    }
    __syncthreads();

    if (t < 64) {
        int eid = e0 + t;
        if (eid < e) {
            float z = part[0][t] + part[1][t] + part[2][t] + part[3][t] + bm2[0];
            out[eid] = 1.0f / (1.0f + __expf(-z));
        }
    }
}

// ---------------- launch ----------------
extern "C" void kernel_launch(void* const* d_in, const int* in_sizes, int n_in,
                              void* d_out, int out_size)
{
    const float* h   = (const float*)d_in[0];
    const int*   src = (const int*)d_in[1];
    const int*   dst = (const int*)d_in[2];
    const float* W1  = (const float*)d_in[3];
    const float* Wr1 = (const float*)d_in[4];
    const float* al1 = (const float*)d_in[5];
    const float* ar1 = (const float*)d_in[6];
    const float* W2  = (const float*)d_in[7];
    const float* al2 = (const float*)d_in[8];
    const float* ar2 = (const float*)d_in[9];
    const float* W3  = (const float*)d_in[10];
    const float* al3 = (const float*)d_in[11];
    const float* ar3 = (const float*)d_in[12];
    const float* Wm1 = (const float*)d_in[13];
    const float* bm1 = (const float*)d_in[14];
    const float* Wm2 = (const float*)d_in[15];
    const float* bm2 = (const float*)d_in[16];
    float* out = (float*)d_out;

    const int n = in_sizes[0] / 128;   // 50000
    const int e = in_sizes[1];         // 800000

    float *ft, *x, *res, *el, *er, *hfp;
    int *deg, *off, *pos, *esrc;
    cudaGetSymbolAddress((void**)&ft,   g_ft);
    cudaGetSymbolAddress((void**)&x,    g_x);
    cudaGetSymbolAddress((void**)&res,  g_res);
    cudaGetSymbolAddress((void**)&el,   g_el);
    cudaGetSymbolAddress((void**)&er,   g_er);
    cudaGetSymbolAddress((void**)&hfp,  g_hf);
    cudaGetSymbolAddress((void**)&deg,  g_deg);
    cudaGetSymbolAddress((void**)&off,  g_off);
    cudaGetSymbolAddress((void**)&pos,  g_pos);
    cudaGetSymbolAddress((void**)&esrc, g_esrc);

    dim3 gg((n + 127) / 128, 2);
    const int ga = (n + 3) / 4;

    zero_int_kernel<<<(n + 1 + 255) / 256, 256>>>(deg, n + 1);
    hist_kernel<<<(e + 255) / 256, 256>>>(dst, deg, e);
    scan_kernel<<<1, 1024>>>(deg, off, pos, n);

    gemm_tc<128, true ><<<gg, 512>>>(h, W1,  ft,  al1, ar1, el, er, n);   // profiled slot
    gemm_tc<128, false><<<gg, 512>>>(h, Wr1, res, nullptr, nullptr, nullptr, nullptr, n);

    scatter_kernel<<<(e + 255) / 256, 256>>>(src, dst, pos, esrc, e);

    agg_kernel<0><<<ga, 256>>>(off, esrc, el, er, ft, res, x, n);
    gemm_tc<256, true><<<gg, 512>>>(x, W2, ft, al2, ar2, el, er, n);
    agg_kernel<0><<<ga, 256>>>(off, esrc, el, er, ft, x, x, n);
    gemm_tc<256, true><<<gg, 512>>>(x, W3, ft, al3, ar3, el, er, n);
    agg_kernel<1><<<ga, 256>>>(off, esrc, el, er, ft, x, hfp, n);

    // Edge MLP via tensor cores -> scores
    mlp_tc_kernel<<<(e + 63) / 64, 256>>>(hfp, src, dst, Wm1, bm1, Wm2, bm2, out, e);
}